// round 1
// baseline (speedup 1.0000x reference)
#include <cuda_runtime.h>
#include <cuda_bf16.h>

#define TPB 256
#define NTRIP 465

// shared-memory layout (float offsets)
#define OFF_W0   0        // 9*64
#define OFF_B0   576
#define OFF_W1   640      // 64*64
#define OFF_B1   4736
#define OFF_W2   4800
#define OFF_B2   8896
#define OFF_W3   8960
#define OFF_B3   13056
#define OFF_W4   13120
#define OFF_B4   17216
#define OFF_W5   17280    // 64*128
#define OFF_B5   25472
#define OFF_B6   25600    // 256
#define OFF_D    25856    // 32*32
#define OFF_Z    26880    // 32
#define OFF_PAIR 26912    // 480 ints
#define OFF_AEV  27392    // 8*256
#define SMEM_FLOATS 29440
#define SMEM_BYTES (SMEM_FLOATS * 4)

__device__ __forceinline__ float fC_cut(float d) {
    // 0.5*cos(pi*d/3.5) + 0.5
    return 0.5f * cosf(0.89759790102565521f * d) + 0.5f;
}

template<int IN, int OUT>
__device__ __forceinline__ void dense(const float* __restrict__ x,
                                      const float* __restrict__ sW,
                                      const float* __restrict__ sB,
                                      float* __restrict__ acc) {
    #pragma unroll
    for (int o = 0; o < OUT; o += 4) {
        float4 bb = *reinterpret_cast<const float4*>(sB + o);
        acc[o] = bb.x; acc[o + 1] = bb.y; acc[o + 2] = bb.z; acc[o + 3] = bb.w;
    }
    #pragma unroll 2
    for (int k = 0; k < IN; k++) {
        float xk = x[k];
        const float4* w4 = reinterpret_cast<const float4*>(sW + k * OUT);
        #pragma unroll
        for (int o = 0; o < OUT; o += 4) {
            float4 w = w4[o >> 2];
            acc[o]     = fmaf(xk, w.x, acc[o]);
            acc[o + 1] = fmaf(xk, w.y, acc[o + 1]);
            acc[o + 2] = fmaf(xk, w.z, acc[o + 2]);
            acc[o + 3] = fmaf(xk, w.w, acc[o + 3]);
        }
    }
}

__global__ void __launch_bounds__(TPB, 1)
Obiwan_84335977825044_kernel(
    const float* __restrict__ gD, const float* __restrict__ gZ,
    const float* __restrict__ W0, const float* __restrict__ b0,
    const float* __restrict__ W1, const float* __restrict__ b1,
    const float* __restrict__ W2, const float* __restrict__ b2,
    const float* __restrict__ W3, const float* __restrict__ b3,
    const float* __restrict__ W4, const float* __restrict__ b4,
    const float* __restrict__ W5, const float* __restrict__ b5,
    const float* __restrict__ W6, const float* __restrict__ b6,
    float* __restrict__ out)
{
    extern __shared__ float sm[];
    const int tid  = threadIdx.x;
    const int lane = tid & 31;
    const int wid  = tid >> 5;
    const int bidx = blockIdx.x;
    const int b    = bidx >> 5;
    const int ictr = bidx & 31;

    // ---- cooperative staging ----
    {
        const float* srcs[15] = {W0, b0, W1, b1, W2, b2, W3, b3, W4, b4, W5, b5, b6,
                                 gD + b * 1024, gZ + b * 32};
        const int offs[15] = {OFF_W0, OFF_B0, OFF_W1, OFF_B1, OFF_W2, OFF_B2, OFF_W3, OFF_B3,
                              OFF_W4, OFF_B4, OFF_W5, OFF_B5, OFF_B6, OFF_D, OFF_Z};
        const int lens[15] = {576, 64, 4096, 64, 4096, 64, 4096, 64, 4096, 64, 8192, 128, 256,
                              1024, 32};
        for (int a = 0; a < 15; a++) {
            const float* s = srcs[a]; float* d = sm + offs[a]; int n = lens[a];
            for (int t = tid; t < n; t += TPB) d[t] = s[t];
        }
    }
    for (int t = tid; t < 2048; t += TPB) sm[OFF_AEV + t] = 0.f;

    int* sPair = reinterpret_cast<int*>(sm + OFF_PAIR);
    if (tid == 0) {
        int p = 0;
        for (int j = 0; j < 32; ++j) {
            if (j == ictr) continue;
            for (int k = j + 1; k < 32; ++k) {
                if (k == ictr) continue;
                sPair[p++] = j | (k << 8);
            }
        }
    }
    __syncthreads();

    const float* sD = sm + OFF_D;
    const float* sZ = sm + OFF_Z;
    const float4* W6v = reinterpret_cast<const float4*>(W6);

    for (int it = 0; it < 2; ++it) {
        int t = it * TPB + tid;
        bool valid = (t < NTRIP);
        int pr = sPair[valid ? t : 0];
        int j = pr & 255;
        int k = pr >> 8;

        float Rij = sD[ictr * 32 + j];
        float Rik = sD[ictr * 32 + k];
        float Rjk = sD[j * 32 + k];
        float zi = sZ[ictr], zj = sZ[j], zk = sZ[k];

        float rij2 = Rij * Rij, rik2 = Rik * Rik, rjk2 = Rjk * Rjk;
        float ci = (rij2 + rik2 - rjk2) / fmaxf(2.f * Rij * Rik, 1e-10f);
        float cj = (rij2 + rjk2 - rik2) / fmaxf(2.f * Rij * Rjk, 1e-10f);
        float ck = (rik2 + rjk2 - rij2) / fmaxf(2.f * Rik * Rjk, 1e-10f);

        float g0 = Rij + Rik + Rjk;
        float g1 = Rij * Rik + Rij * Rjk + Rik * Rjk;
        float g2 = Rij * Rik * Rjk;

        float h0 = zi + zj + zk;
        float h1 = ci + cj + ck;
        float h2 = zi * (zj + zk) + zj * zk - ci * (cj + ck) - cj * ck;
        float h3 = zi * (cj + ck) + ci * (zj + zk) + zj * ck + cj * zk;
        float h4 = zi * (zj * zk - cj * ck) - ci * (zj * ck + cj * zk);
        float h5 = zi * (zj * ck + cj * zk) + ci * (zj * zk - cj * ck);

        float ign = 1.f / (sqrtf(g0 * g0 + g1 * g1 + g2 * g2) + 1e-7f);
        float icn = 1.f / (sqrtf(h0 * h0 + h1 * h1 + h2 * h2 + h3 * h3 + h4 * h4 + h5 * h5) + 1e-7f);

        float smooth = 0.f;
        if (valid && Rij < 3.5f && Rik < 3.5f) smooth = fC_cut(Rij) * fC_cut(Rik);

        // activations in per-thread local arrays (dynamic k indexing OK),
        // accumulators in const-indexed registers.
        float A[64], Bb[64], acc[128];
        A[0] = g0 * ign; A[1] = g1 * ign; A[2] = g2 * ign;
        A[3] = h0 * icn; A[4] = h1 * icn; A[5] = h2 * icn;
        A[6] = h3 * icn; A[7] = h4 * icn; A[8] = h5 * icn;

        dense<9, 64>(A, sm + OFF_W0, sm + OFF_B0, acc);
        #pragma unroll
        for (int o = 0; o < 64; o++) A[o] = tanhf(acc[o]);            // x_res
        dense<64, 64>(A, sm + OFF_W1, sm + OFF_B1, acc);
        #pragma unroll
        for (int o = 0; o < 64; o++) A[o] += tanhf(acc[o]);           // blk1
        dense<64, 64>(A, sm + OFF_W2, sm + OFF_B2, acc);
        #pragma unroll
        for (int o = 0; o < 64; o++) Bb[o] = tanhf(acc[o]);
        dense<64, 64>(Bb, sm + OFF_W3, sm + OFF_B3, acc);
        #pragma unroll
        for (int o = 0; o < 64; o++) Bb[o] = tanhf(acc[o]);
        dense<64, 64>(Bb, sm + OFF_W4, sm + OFF_B4, acc);
        #pragma unroll
        for (int o = 0; o < 64; o++) A[o] += tanhf(acc[o]);           // blk2
        dense<64, 128>(A, sm + OFF_W5, sm + OFF_B5, acc);
        #pragma unroll
        for (int o = 0; o < 64; o++) { A[o] = tanhf(acc[o]); Bb[o] = tanhf(acc[64 + o]); } // blk3

        // final 128->256 layer in 8 chunks of 32 channels; W6 from global (uniform LDG)
        for (int c0 = 0; c0 < 256; c0 += 32) {
            float a6[32];
            #pragma unroll
            for (int o = 0; o < 32; o += 4) {
                float4 bb = *reinterpret_cast<const float4*>(sm + OFF_B6 + c0 + o);
                a6[o] = bb.x; a6[o + 1] = bb.y; a6[o + 2] = bb.z; a6[o + 3] = bb.w;
            }
            #pragma unroll 2
            for (int kk = 0; kk < 64; kk++) {
                float xk = A[kk];
                int base = (kk * 256 + c0) >> 2;
                #pragma unroll
                for (int o = 0; o < 32; o += 4) {
                    float4 w = __ldg(W6v + base + (o >> 2));
                    a6[o]     = fmaf(xk, w.x, a6[o]);
                    a6[o + 1] = fmaf(xk, w.y, a6[o + 1]);
                    a6[o + 2] = fmaf(xk, w.z, a6[o + 2]);
                    a6[o + 3] = fmaf(xk, w.w, a6[o + 3]);
                }
            }
            #pragma unroll 2
            for (int kk = 0; kk < 64; kk++) {
                float xk = Bb[kk];
                int base = ((kk + 64) * 256 + c0) >> 2;
                #pragma unroll
                for (int o = 0; o < 32; o += 4) {
                    float4 w = __ldg(W6v + base + (o >> 2));
                    a6[o]     = fmaf(xk, w.x, a6[o]);
                    a6[o + 1] = fmaf(xk, w.y, a6[o + 1]);
                    a6[o + 2] = fmaf(xk, w.z, a6[o + 2]);
                    a6[o + 3] = fmaf(xk, w.w, a6[o + 3]);
                }
            }
            // cross-lane (cross-triplet) reduce per channel, accumulate per-warp
            float wsum = 0.f;
            #pragma unroll
            for (int o = 0; o < 32; o++) {
                float v = tanhf(a6[o]) * smooth;
                v += __shfl_xor_sync(0xffffffffu, v, 16);
                v += __shfl_xor_sync(0xffffffffu, v, 8);
                v += __shfl_xor_sync(0xffffffffu, v, 4);
                v += __shfl_xor_sync(0xffffffffu, v, 2);
                v += __shfl_xor_sync(0xffffffffu, v, 1);
                if (lane == o) wsum = v;
            }
            sm[OFF_AEV + wid * 256 + c0 + lane] += wsum;
        }
    }

    __syncthreads();
    float s = 0.f;
    #pragma unroll
    for (int w = 0; w < 8; ++w) s += sm[OFF_AEV + w * 256 + tid];
    out[bidx * 256 + tid] = s;
}

extern "C" void kernel_launch(void* const* d_in, const int* in_sizes, int n_in,
                              void* d_out, int out_size) {
    const float* D  = (const float*)d_in[0];
    const float* Z  = (const float*)d_in[1];
    const float* W0 = (const float*)d_in[2];  const float* b0 = (const float*)d_in[3];
    const float* W1 = (const float*)d_in[4];  const float* b1 = (const float*)d_in[5];
    const float* W2 = (const float*)d_in[6];  const float* b2 = (const float*)d_in[7];
    const float* W3 = (const float*)d_in[8];  const float* b3 = (const float*)d_in[9];
    const float* W4 = (const float*)d_in[10]; const float* b4 = (const float*)d_in[11];
    const float* W5 = (const float*)d_in[12]; const float* b5 = (const float*)d_in[13];
    const float* W6 = (const float*)d_in[14]; const float* b6 = (const float*)d_in[15];

    int grid = in_sizes[1];  // B*N = 1024
    cudaFuncSetAttribute(Obiwan_84335977825044_kernel,
                         cudaFuncAttributeMaxDynamicSharedMemorySize, SMEM_BYTES);
    Obiwan_84335977825044_kernel<<<grid, TPB, SMEM_BYTES>>>(
        D, Z, W0, b0, W1, b1, W2, b2, W3, b3, W4, b4, W5, b5, W6, b6,
        (float*)d_out);
}

// round 2
// speedup vs baseline: 1.1683x; 1.1683x over previous
#include <cuda_runtime.h>
#include <cuda_bf16.h>

#define TPB 256

// ---- shared memory layout (float offsets, all 16B-aligned) ----
#define OFF_W0   0        // 9*64
#define OFF_B0   576
#define OFF_W1   640      // 64*64  (W1..W4 + biases, stride 4160)
#define OFF_B1   4736
#define OFF_W2   4800
#define OFF_B2   8896
#define OFF_W3   8960
#define OFF_B3   13056
#define OFF_W4   13120
#define OFF_B4   17216
#define OFF_B5   17280    // 128
#define OFF_B6   17408    // 256
#define OFF_D    17664    // 32*32
#define OFF_Z    18688    // 32
#define OFF_PAIR 18720    // 480 ints
#define OFF_AEV  19200    // 8*256
#define OFF_ACT  21248    // 128 rows * 256 threads (two 64-row planes A|B)
#define SMEM_FLOATS (21248 + 128 * TPB)
#define SMEM_BYTES  (SMEM_FLOATS * 4)

typedef unsigned long long ull;

__device__ __forceinline__ ull pack2(float x) {
    ull r; unsigned u = __float_as_uint(x);
    asm("mov.b64 %0, {%1, %1};" : "=l"(r) : "r"(u));
    return r;
}
__device__ __forceinline__ void ffma2(ull &a, ull x, ull w) {
    asm("fma.rn.f32x2 %0, %1, %2, %0;" : "+l"(a) : "l"(x), "l"(w));
}
__device__ __forceinline__ float2 unpack2(ull a) {
    float2 f;
    asm("mov.b64 {%0, %1}, %2;" : "=f"(f.x), "=f"(f.y) : "l"(a));
    return f;
}
// tanh(x) = 1 - 2/(exp(2x)+1), exp(2x) = 2^(2*log2(e)*x). err ~1e-6.
__device__ __forceinline__ float fast_tanh(float x) {
    float e;
    asm("ex2.approx.f32 %0, %1;" : "=f"(e) : "f"(x * 2.8853900817779268f));
    float r;
    asm("rcp.approx.f32 %0, %1;" : "=f"(r) : "f"(e + 1.0f));
    return fmaf(-2.0f, r, 1.0f);
}
__device__ __forceinline__ float fC_cut(float d) {
    return 0.5f * cosf(0.89759790102565521f * d) + 0.5f;
}

__global__ void __launch_bounds__(TPB, 1)
Obiwan_84335977825044_kernel(
    const float* __restrict__ gD, const float* __restrict__ gZ,
    const float* __restrict__ W0, const float* __restrict__ b0,
    const float* __restrict__ W1, const float* __restrict__ b1,
    const float* __restrict__ W2, const float* __restrict__ b2,
    const float* __restrict__ W3, const float* __restrict__ b3,
    const float* __restrict__ W4, const float* __restrict__ b4,
    const float* __restrict__ W5, const float* __restrict__ b5,
    const float* __restrict__ W6, const float* __restrict__ b6,
    float* __restrict__ out)
{
    extern __shared__ float sm[];
    const int tid  = threadIdx.x;
    const int lane = tid & 31;
    const int wid  = tid >> 5;
    const int bidx = blockIdx.x;
    const int b    = bidx >> 5;
    const int ictr = bidx & 31;

    // ---- cooperative staging of smem-resident weights + per-batch data ----
    {
        const float* srcs[14] = {W0, b0, W1, b1, W2, b2, W3, b3, W4, b4, b5, b6,
                                 gD + b * 1024, gZ + b * 32};
        const int offs[14] = {OFF_W0, OFF_B0, OFF_W1, OFF_B1, OFF_W2, OFF_B2, OFF_W3,
                              OFF_B3, OFF_W4, OFF_B4, OFF_B5, OFF_B6, OFF_D, OFF_Z};
        const int lens[14] = {576, 64, 4096, 64, 4096, 64, 4096, 64, 4096, 64, 128, 256,
                              1024, 32};
        for (int a = 0; a < 14; a++) {
            const float* s = srcs[a]; float* d = sm + offs[a]; int n = lens[a];
            for (int t = tid; t < n; t += TPB) d[t] = s[t];
        }
    }
    for (int t = tid; t < 2048; t += TPB) sm[OFF_AEV + t] = 0.f;

    int* sPair = reinterpret_cast<int*>(sm + OFF_PAIR);
    if (tid == 0) {
        int p = 0;
        for (int j = 0; j < 32; ++j) {
            if (j == ictr) continue;
            for (int k = j + 1; k < 32; ++k) {
                if (k == ictr) continue;
                sPair[p++] = j | (k << 8);
            }
        }
    }
    __syncthreads();

    const float* sD = sm + OFF_D;
    const float* sZ = sm + OFF_Z;
    float* bufA = sm + OFF_ACT;            // rows 0..63   (stride TPB per row)
    float* bufB = sm + OFF_ACT + 64 * TPB; // rows 64..127

    #pragma unroll 1
    for (int it = 0; it < 2; ++it) {
        int t = it * TPB + tid;
        bool valid = (t < 465);
        int pr = sPair[valid ? t : 0];
        int j = pr & 255;
        int k = pr >> 8;

        float Rij = sD[ictr * 32 + j];
        float Rik = sD[ictr * 32 + k];
        float Rjk = sD[j * 32 + k];
        float zi = sZ[ictr], zj = sZ[j], zk = sZ[k];

        float rij2 = Rij * Rij, rik2 = Rik * Rik, rjk2 = Rjk * Rjk;
        float ci = (rij2 + rik2 - rjk2) / fmaxf(2.f * Rij * Rik, 1e-10f);
        float cj = (rij2 + rjk2 - rik2) / fmaxf(2.f * Rij * Rjk, 1e-10f);
        float ck = (rik2 + rjk2 - rij2) / fmaxf(2.f * Rik * Rjk, 1e-10f);

        float g0 = Rij + Rik + Rjk;
        float g1 = Rij * Rik + Rij * Rjk + Rik * Rjk;
        float g2 = Rij * Rik * Rjk;

        float h0 = zi + zj + zk;
        float h1 = ci + cj + ck;
        float h2 = zi * (zj + zk) + zj * zk - ci * (cj + ck) - cj * ck;
        float h3 = zi * (cj + ck) + ci * (zj + zk) + zj * ck + cj * zk;
        float h4 = zi * (zj * zk - cj * ck) - ci * (zj * ck + cj * zk);
        float h5 = zi * (zj * ck + cj * zk) + ci * (zj * zk - cj * ck);

        float ign = 1.f / (sqrtf(g0 * g0 + g1 * g1 + g2 * g2) + 1e-7f);
        float icn = 1.f / (sqrtf(h0 * h0 + h1 * h1 + h2 * h2 + h3 * h3 + h4 * h4 + h5 * h5) + 1e-7f);

        float smooth = 0.f;
        if (valid && Rij < 3.5f && Rik < 3.5f) smooth = fC_cut(Rij) * fC_cut(Rik);

        float in9[9];
        in9[0] = g0 * ign; in9[1] = g1 * ign; in9[2] = g2 * ign;
        in9[3] = h0 * icn; in9[4] = h1 * icn; in9[5] = h2 * icn;
        in9[6] = h3 * icn; in9[7] = h4 * icn; in9[8] = h5 * icn;

        // ---------- L0: 9 -> 64, x_res -> bufA ----------
        {
            ull acc[32];
            #pragma unroll
            for (int q = 0; q < 16; q++) {
                ulonglong2 tt = reinterpret_cast<const ulonglong2*>(sm + OFF_B0)[q];
                acc[2 * q] = tt.x; acc[2 * q + 1] = tt.y;
            }
            #pragma unroll
            for (int kk = 0; kk < 9; kk++) {
                ull x2 = pack2(in9[kk]);
                const ulonglong2* wp = reinterpret_cast<const ulonglong2*>(sm + OFF_W0 + kk * 64);
                #pragma unroll
                for (int q = 0; q < 16; q++) {
                    ulonglong2 w = wp[q];
                    ffma2(acc[2 * q], x2, w.x);
                    ffma2(acc[2 * q + 1], x2, w.y);
                }
            }
            #pragma unroll
            for (int p = 0; p < 32; p++) {
                float2 f = unpack2(acc[p]);
                bufA[(2 * p) * TPB + tid]     = fast_tanh(f.x);
                bufA[(2 * p + 1) * TPB + tid] = fast_tanh(f.y);
            }
        }

        // ---------- L1..L4 (shared rolled body) ----------
        // L1: A -> B = tanh + A   (blk1)
        // L2: B -> A = tanh
        // L3: A -> A = tanh
        // L4: A -> B += tanh      (blk2)
        #pragma unroll 1
        for (int layer = 0; layer < 4; ++layer) {
            const float* W  = sm + OFF_W1 + layer * 4160;
            const float* Bi = W + 4096;
            const float* src = (layer == 1) ? bufB : bufA;
            float x[64];
            #pragma unroll
            for (int o = 0; o < 64; o++) x[o] = src[o * TPB + tid];
            #pragma unroll 1
            for (int c = 0; c < 2; c++) {
                ull acc[16];
                #pragma unroll
                for (int q = 0; q < 8; q++) {
                    ulonglong2 tt = reinterpret_cast<const ulonglong2*>(Bi + c * 32)[q];
                    acc[2 * q] = tt.x; acc[2 * q + 1] = tt.y;
                }
                #pragma unroll
                for (int kk = 0; kk < 64; kk++) {
                    ull x2 = pack2(x[kk]);
                    const ulonglong2* wp = reinterpret_cast<const ulonglong2*>(W + kk * 64 + c * 32);
                    #pragma unroll
                    for (int q = 0; q < 8; q++) {
                        ulonglong2 w = wp[q];
                        ffma2(acc[2 * q], x2, w.x);
                        ffma2(acc[2 * q + 1], x2, w.y);
                    }
                }
                #pragma unroll
                for (int p = 0; p < 16; p++) {
                    float2 f = unpack2(acc[p]);
                    int o = c * 32 + 2 * p;
                    float lo = fast_tanh(f.x), hi = fast_tanh(f.y);
                    if (layer == 0) {
                        bufB[o * TPB + tid]       = lo + bufA[o * TPB + tid];
                        bufB[(o + 1) * TPB + tid] = hi + bufA[(o + 1) * TPB + tid];
                    } else if (layer == 3) {
                        bufB[o * TPB + tid]       += lo;
                        bufB[(o + 1) * TPB + tid] += hi;
                    } else {
                        bufA[o * TPB + tid]       = lo;
                        bufA[(o + 1) * TPB + tid] = hi;
                    }
                }
            }
        }

        // ---------- L5: 64 -> 128 (blk2 in bufB, W5 via uniform LDG), blk3 -> ACT rows 0..127
        {
            float x[64];
            #pragma unroll
            for (int o = 0; o < 64; o++) x[o] = bufB[o * TPB + tid];
            #pragma unroll 1
            for (int c = 0; c < 4; c++) {
                ull acc[16];
                #pragma unroll
                for (int q = 0; q < 8; q++) {
                    ulonglong2 tt = reinterpret_cast<const ulonglong2*>(sm + OFF_B5 + c * 32)[q];
                    acc[2 * q] = tt.x; acc[2 * q + 1] = tt.y;
                }
                #pragma unroll
                for (int kk = 0; kk < 64; kk++) {
                    ull x2 = pack2(x[kk]);
                    const ulonglong2* wp = reinterpret_cast<const ulonglong2*>(W5 + kk * 128 + c * 32);
                    #pragma unroll
                    for (int q = 0; q < 8; q++) {
                        ulonglong2 w = __ldg(wp + q);
                        ffma2(acc[2 * q], x2, w.x);
                        ffma2(acc[2 * q + 1], x2, w.y);
                    }
                }
                #pragma unroll
                for (int p = 0; p < 16; p++) {
                    float2 f = unpack2(acc[p]);
                    int o = c * 32 + 2 * p;
                    sm[OFF_ACT + o * TPB + tid]       = fast_tanh(f.x);
                    sm[OFF_ACT + (o + 1) * TPB + tid] = fast_tanh(f.y);
                }
            }
        }

        // ---------- L6: 128 -> 256, W6 via uniform LDG; tanh*smooth; warp reduce -> AEV
        {
            float x6[128];
            #pragma unroll
            for (int o = 0; o < 128; o++) x6[o] = sm[OFF_ACT + o * TPB + tid];
            #pragma unroll 1
            for (int c = 0; c < 8; c++) {
                ull acc[16];
                #pragma unroll
                for (int q = 0; q < 8; q++) {
                    ulonglong2 tt = reinterpret_cast<const ulonglong2*>(sm + OFF_B6 + c * 32)[q];
                    acc[2 * q] = tt.x; acc[2 * q + 1] = tt.y;
                }
                #pragma unroll
                for (int kk = 0; kk < 128; kk++) {
                    ull x2 = pack2(x6[kk]);
                    const ulonglong2* wp = reinterpret_cast<const ulonglong2*>(W6 + kk * 256 + c * 32);
                    #pragma unroll
                    for (int q = 0; q < 8; q++) {
                        ulonglong2 w = __ldg(wp + q);
                        ffma2(acc[2 * q], x2, w.x);
                        ffma2(acc[2 * q + 1], x2, w.y);
                    }
                }
                float red = 0.f;
                #pragma unroll
                for (int p = 0; p < 16; p++) {
                    float2 f = unpack2(acc[p]);
                    float v0 = fast_tanh(f.x) * smooth;
                    float v1 = fast_tanh(f.y) * smooth;
                    #pragma unroll
                    for (int s = 16; s > 0; s >>= 1) {
                        v0 += __shfl_xor_sync(0xffffffffu, v0, s);
                        v1 += __shfl_xor_sync(0xffffffffu, v1, s);
                    }
                    if (lane == 2 * p)     red = v0;
                    if (lane == 2 * p + 1) red = v1;
                }
                sm[OFF_AEV + wid * 256 + c * 32 + lane] += red;
            }
        }
    }

    __syncthreads();
    float s = 0.f;
    #pragma unroll
    for (int w = 0; w < 8; ++w) s += sm[OFF_AEV + w * 256 + tid];
    out[bidx * 256 + tid] = s;
}

extern "C" void kernel_launch(void* const* d_in, const int* in_sizes, int n_in,
                              void* d_out, int out_size) {
    const float* D  = (const float*)d_in[0];
    const float* Z  = (const float*)d_in[1];
    const float* W0 = (const float*)d_in[2];  const float* b0 = (const float*)d_in[3];
    const float* W1 = (const float*)d_in[4];  const float* b1 = (const float*)d_in[5];
    const float* W2 = (const float*)d_in[6];  const float* b2 = (const float*)d_in[7];
    const float* W3 = (const float*)d_in[8];  const float* b3 = (const float*)d_in[9];
    const float* W4 = (const float*)d_in[10]; const float* b4 = (const float*)d_in[11];
    const float* W5 = (const float*)d_in[12]; const float* b5 = (const float*)d_in[13];
    const float* W6 = (const float*)d_in[14]; const float* b6 = (const float*)d_in[15];

    int grid = in_sizes[1];  // B*N = 1024
    cudaFuncSetAttribute(Obiwan_84335977825044_kernel,
                         cudaFuncAttributeMaxDynamicSharedMemorySize, SMEM_BYTES);
    Obiwan_84335977825044_kernel<<<grid, TPB, SMEM_BYTES>>>(
        D, Z, W0, b0, W1, b1, W2, b2, W3, b3, W4, b4, W5, b5, W6, b6,
        (float*)d_out);
}

// round 3
// speedup vs baseline: 1.1984x; 1.0258x over previous
#include <cuda_runtime.h>
#include <cuda_fp16.h>

#define TPB 512

// ---- shared memory layout (float offsets) ----
#define OFF_W0   0        // 9*64
#define OFF_B0   576
#define OFF_W1   640      // W1..W4 blocks of (4096 W + 64 b), stride 4160
#define OFF_B5   17280    // 128
#define OFF_B6   17408    // 256
#define OFF_D    17664    // 32*32
#define OFF_Z    18688    // 32
#define OFF_PAIR 18720    // 480 ints
#define OFF_AEV  19200    // 16 warps * 256
#define OFF_ACT_BYTES ((19200 + 4096) * 4)   // = 93184, 16B aligned
// ACT: two fp16 planes, 64 rows x 512 cols each
#define PLANE_HALFS (64 * 512)
#define SMEM_BYTES (OFF_ACT_BYTES + 2 * PLANE_HALFS * 2)

typedef unsigned long long ull;

__device__ __forceinline__ ull pack2(float x) {
    ull r; unsigned u = __float_as_uint(x);
    asm("mov.b64 %0, {%1, %1};" : "=l"(r) : "r"(u));
    return r;
}
__device__ __forceinline__ void ffma2(ull &a, ull x, ull w) {
    asm("fma.rn.f32x2 %0, %1, %2, %0;" : "+l"(a) : "l"(x), "l"(w));
}
__device__ __forceinline__ float2 unpack2(ull a) {
    float2 f;
    asm("mov.b64 {%0, %1}, %2;" : "=f"(f.x), "=f"(f.y) : "l"(a));
    return f;
}
// tanh(x) = 1 - 2/(exp(2x)+1); exp via ex2.approx, div via rcp.approx. err ~1e-6.
__device__ __forceinline__ float fast_tanh(float x) {
    float e;
    asm("ex2.approx.f32 %0, %1;" : "=f"(e) : "f"(x * 2.8853900817779268f));
    float r;
    asm("rcp.approx.f32 %0, %1;" : "=f"(r) : "f"(e + 1.0f));
    return fmaf(-2.0f, r, 1.0f);
}
__device__ __forceinline__ float fC_cut(float d) {
    return 0.5f * cosf(0.89759790102565521f * d) + 0.5f;
}

// 64->64 layer: x streamed from fp16 plane, W/b in smem fp32.
// res != nullptr: out = tanh(acc) + res[o]   (read-before-write per element ok)
// park = true:    in-place dst==xs; chunk0 parked in regs, stored after chunk1 reads done
__device__ __noinline__ void mlp64(const __half* __restrict__ xs,
                                   __half* __restrict__ dst,
                                   const __half* __restrict__ res,
                                   const float* __restrict__ W,
                                   const float* __restrict__ Bi,
                                   bool park, int tid)
{
    float parked[32];
    #pragma unroll 1
    for (int c = 0; c < 2; c++) {
        ull acc[16];
        #pragma unroll
        for (int q = 0; q < 8; q++) {
            ulonglong2 tt = reinterpret_cast<const ulonglong2*>(Bi + c * 32)[q];
            acc[2 * q] = tt.x; acc[2 * q + 1] = tt.y;
        }
        #pragma unroll 16
        for (int kk = 0; kk < 64; kk++) {
            ull x2 = pack2(__half2float(xs[kk * TPB + tid]));
            const ulonglong2* wp = reinterpret_cast<const ulonglong2*>(W + kk * 64 + c * 32);
            #pragma unroll
            for (int q = 0; q < 8; q++) {
                ulonglong2 w = wp[q];
                ffma2(acc[2 * q], x2, w.x);
                ffma2(acc[2 * q + 1], x2, w.y);
            }
        }
        if (park && c == 0) {
            #pragma unroll
            for (int p = 0; p < 16; p++) {
                float2 f = unpack2(acc[p]);
                parked[2 * p] = fast_tanh(f.x);
                parked[2 * p + 1] = fast_tanh(f.y);
            }
        } else {
            #pragma unroll
            for (int p = 0; p < 16; p++) {
                float2 f = unpack2(acc[p]);
                int o = c * 32 + 2 * p;
                float lo = fast_tanh(f.x), hi = fast_tanh(f.y);
                if (res) {
                    lo += __half2float(res[o * TPB + tid]);
                    hi += __half2float(res[(o + 1) * TPB + tid]);
                }
                dst[o * TPB + tid]       = __float2half_rn(lo);
                dst[(o + 1) * TPB + tid] = __float2half_rn(hi);
            }
        }
    }
    if (park) {
        #pragma unroll
        for (int o = 0; o < 32; o++) dst[o * TPB + tid] = __float2half_rn(parked[o]);
    }
}

__global__ void __launch_bounds__(TPB, 1)
Obiwan_84335977825044_kernel(
    const float* __restrict__ gD, const float* __restrict__ gZ,
    const float* __restrict__ W0, const float* __restrict__ b0,
    const float* __restrict__ W1, const float* __restrict__ b1,
    const float* __restrict__ W2, const float* __restrict__ b2,
    const float* __restrict__ W3, const float* __restrict__ b3,
    const float* __restrict__ W4, const float* __restrict__ b4,
    const float* __restrict__ W5, const float* __restrict__ b5,
    const float* __restrict__ W6, const float* __restrict__ b6,
    float* __restrict__ out)
{
    extern __shared__ float sm[];
    const int tid  = threadIdx.x;
    const int lane = tid & 31;
    const int wid  = tid >> 5;
    const int bidx = blockIdx.x;
    const int b    = bidx >> 5;
    const int ictr = bidx & 31;

    // ---- staging ----
    {
        const float* srcs[12] = {W0, b0, W1, b1, W2, b2, W3, b3, W4, b4,
                                 gD + b * 1024, gZ + b * 32};
        const int offs[12] = {OFF_W0, OFF_B0, OFF_W1, OFF_W1 + 4096,
                              OFF_W1 + 4160, OFF_W1 + 8256,
                              OFF_W1 + 8320, OFF_W1 + 12416,
                              OFF_W1 + 12480, OFF_W1 + 16576,
                              OFF_D, OFF_Z};
        const int lens[12] = {576, 64, 4096, 64, 4096, 64, 4096, 64, 4096, 64, 1024, 32};
        for (int a = 0; a < 12; a++) {
            const float* s = srcs[a]; float* d = sm + offs[a]; int n = lens[a];
            for (int t = tid; t < n; t += TPB) d[t] = s[t];
        }
        for (int t = tid; t < 128; t += TPB) sm[OFF_B5 + t] = b5[t];
        for (int t = tid; t < 256; t += TPB) sm[OFF_B6 + t] = b6[t];
    }
    int* sPair = reinterpret_cast<int*>(sm + OFF_PAIR);
    if (tid == 0) {
        int p = 0;
        for (int j = 0; j < 32; ++j) {
            if (j == ictr) continue;
            for (int k = j + 1; k < 32; ++k) {
                if (k == ictr) continue;
                sPair[p++] = j | (k << 8);
            }
        }
    }
    __syncthreads();

    const float* sD = sm + OFF_D;
    const float* sZ = sm + OFF_Z;
    __half* PA = reinterpret_cast<__half*>(reinterpret_cast<char*>(sm) + OFF_ACT_BYTES);
    __half* PB = PA + PLANE_HALFS;

    // ---- per-triplet features ----
    bool valid = (tid < 465);
    int pr = sPair[valid ? tid : 0];
    int j = pr & 255;
    int k = pr >> 8;

    float Rij = sD[ictr * 32 + j];
    float Rik = sD[ictr * 32 + k];
    float Rjk = sD[j * 32 + k];
    float zi = sZ[ictr], zj = sZ[j], zk = sZ[k];

    float rij2 = Rij * Rij, rik2 = Rik * Rik, rjk2 = Rjk * Rjk;
    float ci = (rij2 + rik2 - rjk2) / fmaxf(2.f * Rij * Rik, 1e-10f);
    float cj = (rij2 + rjk2 - rik2) / fmaxf(2.f * Rij * Rjk, 1e-10f);
    float ck = (rik2 + rjk2 - rij2) / fmaxf(2.f * Rik * Rjk, 1e-10f);

    float g0 = Rij + Rik + Rjk;
    float g1 = Rij * Rik + Rij * Rjk + Rik * Rjk;
    float g2 = Rij * Rik * Rjk;

    float h0 = zi + zj + zk;
    float h1 = ci + cj + ck;
    float h2 = zi * (zj + zk) + zj * zk - ci * (cj + ck) - cj * ck;
    float h3 = zi * (cj + ck) + ci * (zj + zk) + zj * ck + cj * zk;
    float h4 = zi * (zj * zk - cj * ck) - ci * (zj * ck + cj * zk);
    float h5 = zi * (zj * ck + cj * zk) + ci * (zj * zk - cj * ck);

    float ign = 1.f / (sqrtf(g0 * g0 + g1 * g1 + g2 * g2) + 1e-7f);
    float icn = 1.f / (sqrtf(h0 * h0 + h1 * h1 + h2 * h2 + h3 * h3 + h4 * h4 + h5 * h5) + 1e-7f);

    float smooth = 0.f;
    if (valid && Rij < 3.5f && Rik < 3.5f) smooth = fC_cut(Rij) * fC_cut(Rik);

    float in9[9];
    in9[0] = g0 * ign; in9[1] = g1 * ign; in9[2] = g2 * ign;
    in9[3] = h0 * icn; in9[4] = h1 * icn; in9[5] = h2 * icn;
    in9[6] = h3 * icn; in9[7] = h4 * icn; in9[8] = h5 * icn;

    // ---- L0: 9 -> 64 (W0 smem), x_res -> PA ----
    #pragma unroll 1
    for (int c = 0; c < 2; c++) {
        ull acc[16];
        #pragma unroll
        for (int q = 0; q < 8; q++) {
            ulonglong2 tt = reinterpret_cast<const ulonglong2*>(sm + OFF_B0 + c * 32)[q];
            acc[2 * q] = tt.x; acc[2 * q + 1] = tt.y;
        }
        #pragma unroll
        for (int kk = 0; kk < 9; kk++) {
            ull x2 = pack2(in9[kk]);
            const ulonglong2* wp = reinterpret_cast<const ulonglong2*>(sm + OFF_W0 + kk * 64 + c * 32);
            #pragma unroll
            for (int q = 0; q < 8; q++) {
                ulonglong2 w = wp[q];
                ffma2(acc[2 * q], x2, w.x);
                ffma2(acc[2 * q + 1], x2, w.y);
            }
        }
        #pragma unroll
        for (int p = 0; p < 16; p++) {
            float2 f = unpack2(acc[p]);
            int o = c * 32 + 2 * p;
            PA[o * TPB + tid]       = __float2half_rn(fast_tanh(f.x));
            PA[(o + 1) * TPB + tid] = __float2half_rn(fast_tanh(f.y));
        }
    }

    // ---- L1: PA -> PB = tanh + PA (blk1) ----
    mlp64(PA, PB, PA, sm + OFF_W1,          sm + OFF_W1 + 4096,  false, tid);
    // ---- L2: PB -> PA = tanh ----
    mlp64(PB, PA, nullptr, sm + OFF_W1 + 4160,  sm + OFF_W1 + 8256,  false, tid);
    // ---- L3: PA -> PA in-place (park) ----
    mlp64(PA, PA, nullptr, sm + OFF_W1 + 8320,  sm + OFF_W1 + 12416, true,  tid);
    // ---- L4: PA -> PB = tanh + PB (blk2, element-wise read-before-write) ----
    mlp64(PA, PB, PB, sm + OFF_W1 + 12480, sm + OFF_W1 + 16576, false, tid);

    // ---- L5: 64 -> 128 (x = PB blk2, W5 global uniform LDG) ----
    // blk3 rows 0..63 -> PA, rows 64..127 -> PB (c2 parked, c3 stored after reads)
    {
        float parked[32];
        #pragma unroll 1
        for (int c = 0; c < 4; c++) {
            ull acc[16];
            #pragma unroll
            for (int q = 0; q < 8; q++) {
                ulonglong2 tt = reinterpret_cast<const ulonglong2*>(sm + OFF_B5 + c * 32)[q];
                acc[2 * q] = tt.x; acc[2 * q + 1] = tt.y;
            }
            #pragma unroll 16
            for (int kk = 0; kk < 64; kk++) {
                ull x2 = pack2(__half2float(PB[kk * TPB + tid]));
                const ulonglong2* wp = reinterpret_cast<const ulonglong2*>(W5 + kk * 128 + c * 32);
                #pragma unroll
                for (int q = 0; q < 8; q++) {
                    ulonglong2 w = __ldg(wp + q);
                    ffma2(acc[2 * q], x2, w.x);
                    ffma2(acc[2 * q + 1], x2, w.y);
                }
            }
            if (c < 2) {
                #pragma unroll
                for (int p = 0; p < 16; p++) {
                    float2 f = unpack2(acc[p]);
                    int o = c * 32 + 2 * p;
                    PA[o * TPB + tid]       = __float2half_rn(fast_tanh(f.x));
                    PA[(o + 1) * TPB + tid] = __float2half_rn(fast_tanh(f.y));
                }
            } else if (c == 2) {
                #pragma unroll
                for (int p = 0; p < 16; p++) {
                    float2 f = unpack2(acc[p]);
                    parked[2 * p] = fast_tanh(f.x);
                    parked[2 * p + 1] = fast_tanh(f.y);
                }
            } else {
                #pragma unroll
                for (int p = 0; p < 16; p++) {
                    float2 f = unpack2(acc[p]);
                    int o = 32 + 2 * p;
                    PB[o * TPB + tid]       = __float2half_rn(fast_tanh(f.x));
                    PB[(o + 1) * TPB + tid] = __float2half_rn(fast_tanh(f.y));
                }
                #pragma unroll
                for (int o = 0; o < 32; o++) PB[o * TPB + tid] = __float2half_rn(parked[o]);
            }
        }
    }

    // ---- L6: 128 -> 256 (x = PA rows 0-63 ++ PB rows 0-63, W6 global), reduce -> AEV ----
    #pragma unroll 1
    for (int c = 0; c < 8; c++) {
        ull acc[16];
        #pragma unroll
        for (int q = 0; q < 8; q++) {
            ulonglong2 tt = reinterpret_cast<const ulonglong2*>(sm + OFF_B6 + c * 32)[q];
            acc[2 * q] = tt.x; acc[2 * q + 1] = tt.y;
        }
        #pragma unroll 1
        for (int kh = 0; kh < 2; kh++) {
            const __half* xp = kh ? PB : PA;
            const float* wbase = W6 + kh * 64 * 256 + c * 32;
            #pragma unroll 16
            for (int kk = 0; kk < 64; kk++) {
                ull x2 = pack2(__half2float(xp[kk * TPB + tid]));
                const ulonglong2* wp = reinterpret_cast<const ulonglong2*>(wbase + kk * 256);
                #pragma unroll
                for (int q = 0; q < 8; q++) {
                    ulonglong2 w = __ldg(wp + q);
                    ffma2(acc[2 * q], x2, w.x);
                    ffma2(acc[2 * q + 1], x2, w.y);
                }
            }
        }
        float red = 0.f;
        #pragma unroll
        for (int p = 0; p < 16; p++) {
            float2 f = unpack2(acc[p]);
            float v0 = fast_tanh(f.x) * smooth;
            float v1 = fast_tanh(f.y) * smooth;
            #pragma unroll
            for (int s = 16; s > 0; s >>= 1) {
                v0 += __shfl_xor_sync(0xffffffffu, v0, s);
                v1 += __shfl_xor_sync(0xffffffffu, v1, s);
            }
            if (lane == 2 * p)     red = v0;
            if (lane == 2 * p + 1) red = v1;
        }
        sm[OFF_AEV + wid * 256 + c * 32 + lane] = red;
    }

    __syncthreads();
    if (tid < 256) {
        float s = 0.f;
        #pragma unroll
        for (int w = 0; w < 16; ++w) s += sm[OFF_AEV + w * 256 + tid];
        out[bidx * 256 + tid] = s;
    }
}

extern "C" void kernel_launch(void* const* d_in, const int* in_sizes, int n_in,
                              void* d_out, int out_size) {
    const float* D  = (const float*)d_in[0];
    const float* Z  = (const float*)d_in[1];
    const float* W0 = (const float*)d_in[2];  const float* b0 = (const float*)d_in[3];
    const float* W1 = (const float*)d_in[4];  const float* b1 = (const float*)d_in[5];
    const float* W2 = (const float*)d_in[6];  const float* b2 = (const float*)d_in[7];
    const float* W3 = (const float*)d_in[8];  const float* b3 = (const float*)d_in[9];
    const float* W4 = (const float*)d_in[10]; const float* b4 = (const float*)d_in[11];
    const float* W5 = (const float*)d_in[12]; const float* b5 = (const float*)d_in[13];
    const float* W6 = (const float*)d_in[14]; const float* b6 = (const float*)d_in[15];

    int grid = in_sizes[1];  // B*N = 1024
    cudaFuncSetAttribute(Obiwan_84335977825044_kernel,
                         cudaFuncAttributeMaxDynamicSharedMemorySize, SMEM_BYTES);
    Obiwan_84335977825044_kernel<<<grid, TPB, SMEM_BYTES>>>(
        D, Z, W0, b0, W1, b1, W2, b2, W3, b3, W4, b4, W5, b5, W6, b6,
        (float*)d_out);
}

// round 4
// speedup vs baseline: 6.3757x; 5.3203x over previous
#include <cuda_runtime.h>
#include <cuda_fp16.h>
#include <stdint.h>

#define TPB 256

// ---- dynamic smem layout (byte offsets) ----
#define OFF_W14    0        // W1..W4 fp16, each [64][72], 9216 B apiece
#define OFF_W5     36864    // W5 fp16 [64][136]
#define OFF_P0     54272    // plane0 fp16 [512][72]
#define OFF_P1     128000   // plane1 fp16 [512][72]
#define OFF_W0     201728   // W0 fp32 [9][64]
#define OFF_BIAS   204032   // 704 fp32: b0|b1|b2|b3|b4|b5|b6
#define OFF_SMOOTH 206848   // 512 fp32
#define OFF_AEV    208896   // 8*256 fp32
#define OFF_D      217088   // 1024 fp32
#define OFF_Z      221184   // 32 fp32
#define OFF_PAIR   221312   // 480 int
#define SMEM_BYTES 223232

// W6 pre-packed into mma B-fragment layout: uint2 per (ntile, kstep, lane)
__device__ uint2 g_w6frag[32 * 8 * 32];

__device__ __forceinline__ uint32_t cvta_sh(const void* p) {
    return (uint32_t)__cvta_generic_to_shared(p);
}
__device__ __forceinline__ void ldsm4(uint32_t* r, uint32_t addr) {
    asm volatile("ldmatrix.sync.aligned.m8n8.x4.shared.b16 {%0,%1,%2,%3}, [%4];"
        : "=r"(r[0]), "=r"(r[1]), "=r"(r[2]), "=r"(r[3]) : "r"(addr));
}
__device__ __forceinline__ void ldsm4t(uint32_t* r, uint32_t addr) {
    asm volatile("ldmatrix.sync.aligned.m8n8.x4.trans.shared.b16 {%0,%1,%2,%3}, [%4];"
        : "=r"(r[0]), "=r"(r[1]), "=r"(r[2]), "=r"(r[3]) : "r"(addr));
}
__device__ __forceinline__ void mma16816(float* d, const uint32_t* a, const uint32_t* b) {
    asm volatile("mma.sync.aligned.m16n8k16.row.col.f32.f16.f16.f32 "
        "{%0,%1,%2,%3}, {%4,%5,%6,%7}, {%8,%9}, {%0,%1,%2,%3};"
        : "+f"(d[0]), "+f"(d[1]), "+f"(d[2]), "+f"(d[3])
        : "r"(a[0]), "r"(a[1]), "r"(a[2]), "r"(a[3]), "r"(b[0]), "r"(b[1]));
}
// tanh(x) = 1 - 2/(exp(2x)+1), 2 MUFU, rel err ~1e-6
__device__ __forceinline__ float fast_tanh(float x) {
    float e;
    asm("ex2.approx.f32 %0, %1;" : "=f"(e) : "f"(x * 2.8853900817779268f));
    float r;
    asm("rcp.approx.f32 %0, %1;" : "=f"(r) : "f"(e + 1.0f));
    return fmaf(-2.0f, r, 1.0f);
}
__device__ __forceinline__ float fC_cut(float d) {
    return 0.5f * cosf(0.89759790102565521f * d) + 0.5f;
}

// prep: pack W6 (fp32 [128][256]) into mma B fragments (fp16)
__global__ void w6_prep(const float* __restrict__ W6) {
    int nt = blockIdx.x;            // 0..31 (n-tile of 8 cols)
    int ks = threadIdx.x >> 5;      // 0..7  (k-step of 16)
    int l  = threadIdx.x & 31;
    int n = nt * 8 + (l >> 2);
    int k = ks * 16 + (l & 3) * 2;
    __half2 b0 = __floats2half2_rn(W6[k * 256 + n], W6[(k + 1) * 256 + n]);
    __half2 b1 = __floats2half2_rn(W6[(k + 8) * 256 + n], W6[(k + 9) * 256 + n]);
    uint2 u;
    u.x = *reinterpret_cast<uint32_t*>(&b0);
    u.y = *reinterpret_cast<uint32_t*>(&b1);
    g_w6frag[(nt * 8 + ks) * 32 + l] = u;
}

// 64->64 mma layer for one warp (64 rows).
// MODE 0: dst = tanh(acc); MODE 1: dst = tanh(acc) + res; MODE 2: in-place (src==dst, park chunk0)
template<int MODE>
__device__ __forceinline__ void layer64(char* sm8, int srcOff, int dstOff, int resOff,
                                        int wOff, const float* bias, int lane, int R0)
{
    const int gid = lane >> 2, tig = lane & 3;
    uint32_t aBase = cvta_sh(sm8 + srcOff) + (R0 + (lane & 15)) * 144 + (lane >> 4) * 16;
    uint32_t bBase = cvta_sh(sm8 + wOff) + (lane & 15) * 144 + (lane >> 4) * 16;
    uint32_t parked[32];
    __syncwarp();
    #pragma unroll
    for (int nch = 0; nch < 2; nch++) {
        float acc[4][4][4];
        #pragma unroll
        for (int nt = 0; nt < 4; nt++) {
            float2 bc = *reinterpret_cast<const float2*>(bias + nch * 32 + nt * 8 + tig * 2);
            #pragma unroll
            for (int m = 0; m < 4; m++) {
                acc[m][nt][0] = bc.x; acc[m][nt][1] = bc.y;
                acc[m][nt][2] = bc.x; acc[m][nt][3] = bc.y;
            }
        }
        #pragma unroll 1
        for (int ks = 0; ks < 4; ks++) {
            uint32_t a[4][4];
            #pragma unroll
            for (int m = 0; m < 4; m++) ldsm4(a[m], aBase + m * 2304 + ks * 32);
            uint32_t bfr[4][2];
            #pragma unroll
            for (int p = 0; p < 2; p++) {
                uint32_t r[4];
                ldsm4t(r, bBase + ks * 2304 + (nch * 32 + p * 16) * 2);
                bfr[p * 2][0] = r[0]; bfr[p * 2][1] = r[1];
                bfr[p * 2 + 1][0] = r[2]; bfr[p * 2 + 1][1] = r[3];
            }
            #pragma unroll
            for (int m = 0; m < 4; m++)
                #pragma unroll
                for (int nt = 0; nt < 4; nt++)
                    mma16816(acc[m][nt], a[m], bfr[nt]);
        }
        __syncwarp();
        #pragma unroll
        for (int m = 0; m < 4; m++) {
            #pragma unroll
            for (int nt = 0; nt < 4; nt++) {
                int col = nch * 32 + nt * 8 + tig * 2;
                int row = R0 + m * 16 + gid;
                float v0 = fast_tanh(acc[m][nt][0]);
                float v1 = fast_tanh(acc[m][nt][1]);
                float v2 = fast_tanh(acc[m][nt][2]);
                float v3 = fast_tanh(acc[m][nt][3]);
                if (MODE == 1) {
                    float2 r0 = __half22float2(*(__half2*)(sm8 + resOff + row * 144 + col * 2));
                    float2 r1 = __half22float2(*(__half2*)(sm8 + resOff + (row + 8) * 144 + col * 2));
                    v0 += r0.x; v1 += r0.y; v2 += r1.x; v3 += r1.y;
                }
                __half2 p01 = __floats2half2_rn(v0, v1);
                __half2 p23 = __floats2half2_rn(v2, v3);
                if (MODE == 2 && nch == 0) {
                    parked[(m * 4 + nt) * 2]     = *reinterpret_cast<uint32_t*>(&p01);
                    parked[(m * 4 + nt) * 2 + 1] = *reinterpret_cast<uint32_t*>(&p23);
                } else {
                    *(__half2*)(sm8 + dstOff + row * 144 + col * 2) = p01;
                    *(__half2*)(sm8 + dstOff + (row + 8) * 144 + col * 2) = p23;
                }
            }
        }
    }
    if (MODE == 2) {
        __syncwarp();
        #pragma unroll
        for (int m = 0; m < 4; m++)
            #pragma unroll
            for (int nt = 0; nt < 4; nt++) {
                int col = nt * 8 + tig * 2;
                int row = R0 + m * 16 + gid;
                *(uint32_t*)(sm8 + dstOff + row * 144 + col * 2)       = parked[(m * 4 + nt) * 2];
                *(uint32_t*)(sm8 + dstOff + (row + 8) * 144 + col * 2) = parked[(m * 4 + nt) * 2 + 1];
            }
    }
}

// L5: 64 -> 128. src = P1 (blk2). dst: cols 0-63 -> P0, cols 64-127 -> P1 (chunk2 parked).
__device__ __forceinline__ void layer5(char* sm8, const float* bias, int lane, int R0)
{
    const int gid = lane >> 2, tig = lane & 3;
    uint32_t aBase = cvta_sh(sm8 + OFF_P1) + (R0 + (lane & 15)) * 144 + (lane >> 4) * 16;
    uint32_t bBase = cvta_sh(sm8 + OFF_W5) + (lane & 15) * 272 + (lane >> 4) * 16;
    uint32_t parked[32];
    __syncwarp();
    #pragma unroll 1
    for (int nch = 0; nch < 4; nch++) {
        float acc[4][4][4];
        #pragma unroll
        for (int nt = 0; nt < 4; nt++) {
            float2 bc = *reinterpret_cast<const float2*>(bias + nch * 32 + nt * 8 + tig * 2);
            #pragma unroll
            for (int m = 0; m < 4; m++) {
                acc[m][nt][0] = bc.x; acc[m][nt][1] = bc.y;
                acc[m][nt][2] = bc.x; acc[m][nt][3] = bc.y;
            }
        }
        #pragma unroll 1
        for (int ks = 0; ks < 4; ks++) {
            uint32_t a[4][4];
            #pragma unroll
            for (int m = 0; m < 4; m++) ldsm4(a[m], aBase + m * 2304 + ks * 32);
            uint32_t bfr[4][2];
            #pragma unroll
            for (int p = 0; p < 2; p++) {
                uint32_t r[4];
                ldsm4t(r, bBase + ks * 4352 + (nch * 32 + p * 16) * 2);
                bfr[p * 2][0] = r[0]; bfr[p * 2][1] = r[1];
                bfr[p * 2 + 1][0] = r[2]; bfr[p * 2 + 1][1] = r[3];
            }
            #pragma unroll
            for (int m = 0; m < 4; m++)
                #pragma unroll
                for (int nt = 0; nt < 4; nt++)
                    mma16816(acc[m][nt], a[m], bfr[nt]);
        }
        int dstOff = (nch < 2) ? OFF_P0 : OFF_P1;
        int dcol = (nch & 1) * 32;
        __syncwarp();
        #pragma unroll
        for (int m = 0; m < 4; m++) {
            #pragma unroll
            for (int nt = 0; nt < 4; nt++) {
                int col = dcol + nt * 8 + tig * 2;
                int row = R0 + m * 16 + gid;
                __half2 p01 = __floats2half2_rn(fast_tanh(acc[m][nt][0]), fast_tanh(acc[m][nt][1]));
                __half2 p23 = __floats2half2_rn(fast_tanh(acc[m][nt][2]), fast_tanh(acc[m][nt][3]));
                if (nch == 2) {
                    parked[(m * 4 + nt) * 2]     = *reinterpret_cast<uint32_t*>(&p01);
                    parked[(m * 4 + nt) * 2 + 1] = *reinterpret_cast<uint32_t*>(&p23);
                } else {
                    *(__half2*)(sm8 + dstOff + row * 144 + col * 2) = p01;
                    *(__half2*)(sm8 + dstOff + (row + 8) * 144 + col * 2) = p23;
                }
            }
        }
    }
    __syncwarp();
    #pragma unroll
    for (int m = 0; m < 4; m++)
        #pragma unroll
        for (int nt = 0; nt < 4; nt++) {
            int col = nt * 8 + tig * 2;
            int row = R0 + m * 16 + gid;
            *(uint32_t*)(sm8 + OFF_P1 + row * 144 + col * 2)       = parked[(m * 4 + nt) * 2];
            *(uint32_t*)(sm8 + OFF_P1 + (row + 8) * 144 + col * 2) = parked[(m * 4 + nt) * 2 + 1];
        }
}

// L6: 128 -> 256, B frags from g_w6frag (global), epilogue: tanh*smooth + row-reduction -> AEV
__device__ __forceinline__ void layer6(char* sm8, const float* bias, int lane, int R0, int wid)
{
    const int gid = lane >> 2, tig = lane & 3;
    uint32_t aBase0 = cvta_sh(sm8 + OFF_P0) + (R0 + (lane & 15)) * 144 + (lane >> 4) * 16;
    uint32_t aBase1 = cvta_sh(sm8 + OFF_P1) + (R0 + (lane & 15)) * 144 + (lane >> 4) * 16;
    const float* smoothF = (const float*)(sm8 + OFF_SMOOTH);
    float* aev = (float*)(sm8 + OFF_AEV) + wid * 256;
    float s[4][2];
    __syncwarp();
    #pragma unroll
    for (int m = 0; m < 4; m++) {
        s[m][0] = smoothF[R0 + m * 16 + gid];
        s[m][1] = smoothF[R0 + m * 16 + gid + 8];
    }
    #pragma unroll 1
    for (int nch = 0; nch < 8; nch++) {
        float acc[4][4][4];
        #pragma unroll
        for (int nt = 0; nt < 4; nt++) {
            float2 bc = *reinterpret_cast<const float2*>(bias + nch * 32 + nt * 8 + tig * 2);
            #pragma unroll
            for (int m = 0; m < 4; m++) {
                acc[m][nt][0] = bc.x; acc[m][nt][1] = bc.y;
                acc[m][nt][2] = bc.x; acc[m][nt][3] = bc.y;
            }
        }
        #pragma unroll 1
        for (int ks = 0; ks < 8; ks++) {
            uint32_t ab = (ks < 4) ? (aBase0 + ks * 32) : (aBase1 + (ks - 4) * 32);
            uint32_t a[4][4];
            #pragma unroll
            for (int m = 0; m < 4; m++) ldsm4(a[m], ab + m * 2304);
            uint2 bw[4];
            #pragma unroll
            for (int nt = 0; nt < 4; nt++)
                bw[nt] = g_w6frag[((nch * 4 + nt) * 8 + ks) * 32 + lane];
            #pragma unroll
            for (int m = 0; m < 4; m++)
                #pragma unroll
                for (int nt = 0; nt < 4; nt++) {
                    uint32_t bb[2] = {bw[nt].x, bw[nt].y};
                    mma16816(acc[m][nt], a[m], bb);
                }
        }
        float t0[4] = {0.f, 0.f, 0.f, 0.f}, t1[4] = {0.f, 0.f, 0.f, 0.f};
        #pragma unroll
        for (int m = 0; m < 4; m++)
            #pragma unroll
            for (int nt = 0; nt < 4; nt++) {
                t0[nt] += fast_tanh(acc[m][nt][0]) * s[m][0] + fast_tanh(acc[m][nt][2]) * s[m][1];
                t1[nt] += fast_tanh(acc[m][nt][1]) * s[m][0] + fast_tanh(acc[m][nt][3]) * s[m][1];
            }
        #pragma unroll
        for (int nt = 0; nt < 4; nt++) {
            #pragma unroll
            for (int sh = 4; sh < 32; sh <<= 1) {
                t0[nt] += __shfl_xor_sync(0xffffffffu, t0[nt], sh);
                t1[nt] += __shfl_xor_sync(0xffffffffu, t1[nt], sh);
            }
        }
        if (lane < 4) {
            #pragma unroll
            for (int nt = 0; nt < 4; nt++) {
                int col = nch * 32 + nt * 8 + lane * 2;
                aev[col] = t0[nt];
                aev[col + 1] = t1[nt];
            }
        }
    }
}

__global__ void __launch_bounds__(TPB, 1)
Obiwan_84335977825044_kernel(
    const float* __restrict__ gD, const float* __restrict__ gZ,
    const float* __restrict__ W0, const float* __restrict__ b0,
    const float* __restrict__ W1, const float* __restrict__ b1,
    const float* __restrict__ W2, const float* __restrict__ b2,
    const float* __restrict__ W3, const float* __restrict__ b3,
    const float* __restrict__ W4, const float* __restrict__ b4,
    const float* __restrict__ W5, const float* __restrict__ b5,
    const float* __restrict__ b6,
    float* __restrict__ out)
{
    extern __shared__ char sm8[];
    const int tid  = threadIdx.x;
    const int lane = tid & 31;
    const int wid  = tid >> 5;
    const int bidx = blockIdx.x;
    const int b    = bidx >> 5;
    const int ictr = bidx & 31;

    float* W0F   = (float*)(sm8 + OFF_W0);
    float* biasF = (float*)(sm8 + OFF_BIAS);
    float* smF   = (float*)(sm8 + OFF_SMOOTH);
    float* sDF   = (float*)(sm8 + OFF_D);
    float* sZF   = (float*)(sm8 + OFF_Z);
    int*   pairI = (int*)(sm8 + OFF_PAIR);

    // ---- staging: fp16 weight conversion + fp32 small data ----
    {
        const float* wsrc[4] = {W1, W2, W3, W4};
        for (int L = 0; L < 4; L++) {
            __half* wd = (__half*)(sm8 + OFF_W14 + L * 9216);
            const float* ws = wsrc[L];
            for (int i = tid; i < 4096; i += TPB)
                wd[(i >> 6) * 72 + (i & 63)] = __float2half_rn(ws[i]);
        }
        __half* w5d = (__half*)(sm8 + OFF_W5);
        for (int i = tid; i < 8192; i += TPB)
            w5d[(i >> 7) * 136 + (i & 127)] = __float2half_rn(W5[i]);
        for (int i = tid; i < 576; i += TPB) W0F[i] = W0[i];
        for (int i = tid; i < 64; i += TPB) {
            biasF[i] = b0[i]; biasF[64 + i] = b1[i]; biasF[128 + i] = b2[i];
            biasF[192 + i] = b3[i]; biasF[256 + i] = b4[i];
        }
        for (int i = tid; i < 128; i += TPB) biasF[320 + i] = b5[i];
        for (int i = tid; i < 256; i += TPB) biasF[448 + i] = b6[i];
        for (int i = tid; i < 1024; i += TPB) sDF[i] = gD[b * 1024 + i];
        for (int i = tid; i < 32; i += TPB) sZF[i] = gZ[b * 32 + i];
        if (tid == 0) {
            int p = 0;
            for (int j = 0; j < 32; ++j) {
                if (j == ictr) continue;
                for (int k = j + 1; k < 32; ++k) {
                    if (k == ictr) continue;
                    pairI[p++] = j | (k << 8);
                }
            }
        }
    }
    __syncthreads();

    // ---- L0 (scalar fp32): rows 2*tid, 2*tid+1 -> P0, plus smooth[] ----
    #pragma unroll 1
    for (int rr = 0; rr < 2; rr++) {
        int r = 2 * tid + rr;
        bool valid = (r < 465);
        int pr = pairI[valid ? r : 0];
        int j = pr & 255;
        int k = pr >> 8;

        float Rij = sDF[ictr * 32 + j];
        float Rik = sDF[ictr * 32 + k];
        float Rjk = sDF[j * 32 + k];
        float zi = sZF[ictr], zj = sZF[j], zk = sZF[k];

        float rij2 = Rij * Rij, rik2 = Rik * Rik, rjk2 = Rjk * Rjk;
        float ci = (rij2 + rik2 - rjk2) / fmaxf(2.f * Rij * Rik, 1e-10f);
        float cj = (rij2 + rjk2 - rik2) / fmaxf(2.f * Rij * Rjk, 1e-10f);
        float ck = (rik2 + rjk2 - rij2) / fmaxf(2.f * Rik * Rjk, 1e-10f);

        float g0 = Rij + Rik + Rjk;
        float g1 = Rij * Rik + Rij * Rjk + Rik * Rjk;
        float g2 = Rij * Rik * Rjk;

        float h0 = zi + zj + zk;
        float h1 = ci + cj + ck;
        float h2 = zi * (zj + zk) + zj * zk - ci * (cj + ck) - cj * ck;
        float h3 = zi * (cj + ck) + ci * (zj + zk) + zj * ck + cj * zk;
        float h4 = zi * (zj * zk - cj * ck) - ci * (zj * ck + cj * zk);
        float h5 = zi * (zj * ck + cj * zk) + ci * (zj * zk - cj * ck);

        float ign = 1.f / (sqrtf(g0 * g0 + g1 * g1 + g2 * g2) + 1e-7f);
        float icn = 1.f / (sqrtf(h0 * h0 + h1 * h1 + h2 * h2 + h3 * h3 + h4 * h4 + h5 * h5) + 1e-7f);

        float smooth = 0.f;
        if (valid && Rij < 3.5f && Rik < 3.5f) smooth = fC_cut(Rij) * fC_cut(Rik);
        smF[r] = smooth;

        float in9[9];
        in9[0] = g0 * ign; in9[1] = g1 * ign; in9[2] = g2 * ign;
        in9[3] = h0 * icn; in9[4] = h1 * icn; in9[5] = h2 * icn;
        in9[6] = h3 * icn; in9[7] = h4 * icn; in9[8] = h5 * icn;
        if (!valid) {
            #pragma unroll
            for (int q = 0; q < 9; q++) in9[q] = 0.f;
        }

        float acc[64];
        #pragma unroll
        for (int o = 0; o < 64; o += 4) {
            float4 bb = *reinterpret_cast<const float4*>(biasF + o);
            acc[o] = bb.x; acc[o + 1] = bb.y; acc[o + 2] = bb.z; acc[o + 3] = bb.w;
        }
        #pragma unroll 1
        for (int kk = 0; kk < 9; kk++) {
            float xk = in9[kk];
            const float4* w4 = reinterpret_cast<const float4*>(W0F + kk * 64);
            #pragma unroll
            for (int o = 0; o < 64; o += 4) {
                float4 w = w4[o >> 2];
                acc[o]     = fmaf(xk, w.x, acc[o]);
                acc[o + 1] = fmaf(xk, w.y, acc[o + 1]);
                acc[o + 2] = fmaf(xk, w.z, acc[o + 2]);
                acc[o + 3] = fmaf(xk, w.w, acc[o + 3]);
            }
        }
        #pragma unroll
        for (int o = 0; o < 64; o += 2) {
            __half2 h = __floats2half2_rn(fast_tanh(acc[o]), fast_tanh(acc[o + 1]));
            *(__half2*)(sm8 + OFF_P0 + r * 144 + o * 2) = h;
        }
    }

    // ---- MLP via mma, each warp owns rows [64*wid, 64*wid+64) ----
    const int R0 = wid * 64;
    layer64<1>(sm8, OFF_P0, OFF_P1, OFF_P0, OFF_W14 + 0,     biasF + 64,  lane, R0); // blk1
    layer64<0>(sm8, OFF_P1, OFF_P0, 0,      OFF_W14 + 9216,  biasF + 128, lane, R0);
    layer64<2>(sm8, OFF_P0, OFF_P0, 0,      OFF_W14 + 18432, biasF + 192, lane, R0);
    layer64<1>(sm8, OFF_P0, OFF_P1, OFF_P1, OFF_W14 + 27648, biasF + 256, lane, R0); // blk2
    layer5(sm8, biasF + 320, lane, R0);                                              // blk3
    layer6(sm8, biasF + 448, lane, R0, wid);

    // ---- final reduction across warps ----
    __syncthreads();
    float* aevF = (float*)(sm8 + OFF_AEV);
    float s = 0.f;
    #pragma unroll
    for (int w = 0; w < 8; ++w) s += aevF[w * 256 + tid];
    out[bidx * 256 + tid] = s;
}

extern "C" void kernel_launch(void* const* d_in, const int* in_sizes, int n_in,
                              void* d_out, int out_size) {
    const float* D  = (const float*)d_in[0];
    const float* Z  = (const float*)d_in[1];
    const float* W0 = (const float*)d_in[2];  const float* b0 = (const float*)d_in[3];
    const float* W1 = (const float*)d_in[4];  const float* b1 = (const float*)d_in[5];
    const float* W2 = (const float*)d_in[6];  const float* b2 = (const float*)d_in[7];
    const float* W3 = (const float*)d_in[8];  const float* b3 = (const float*)d_in[9];
    const float* W4 = (const float*)d_in[10]; const float* b4 = (const float*)d_in[11];
    const float* W5 = (const float*)d_in[12]; const float* b5 = (const float*)d_in[13];
    const float* W6 = (const float*)d_in[14]; const float* b6 = (const float*)d_in[15];

    w6_prep<<<32, TPB>>>(W6);

    int grid = in_sizes[1];  // B*N = 1024
    cudaFuncSetAttribute(Obiwan_84335977825044_kernel,
                         cudaFuncAttributeMaxDynamicSharedMemorySize, SMEM_BYTES);
    Obiwan_84335977825044_kernel<<<grid, TPB, SMEM_BYTES>>>(
        D, Z, W0, b0, W1, b1, W2, b2, W3, b3, W4, b4, W5, b5, b6,
        (float*)d_out);
}

// round 5
// speedup vs baseline: 12.5728x; 1.9720x over previous
#include <cuda_runtime.h>
#include <cuda_fp16.h>
#include <stdint.h>

#define TPB 256

// ---- dynamic smem layout (byte offsets) ----
#define OFF_P0     0         // plane0 fp16 [256][72]
#define OFF_P1     36864     // plane1 fp16 [256][72]
#define OFF_D      73728     // 1024 fp32
#define OFF_Z      77824     // 32 fp32
#define OFF_SMOOTH 77952     // 256 fp32
#define OFF_BIAS   78976     // 704 fp32: b0|b1|b2|b3|b4|b5|b6
#define OFF_AEV    81792     // 8 warps * 256 fp32
#define OFF_W0     89984     // 576 fp32
#define SMEM_BYTES 92288

// weight fragments (B operand of m16n8k16), packed once per launch
__device__ uint2 g_w14frag[4 * 1024];   // W1..W4: 8 ntiles * 4 ksteps * 32 lanes
__device__ uint2 g_w5frag[2048];        // W5: 16 ntiles * 4 ksteps * 32
__device__ uint2 g_w6frag[8192];        // W6: 32 ntiles * 8 ksteps * 32
__device__ float g_part[2048 * 256];    // per-block partial AEV

__device__ __forceinline__ uint32_t cvta_sh(const void* p) {
    return (uint32_t)__cvta_generic_to_shared(p);
}
__device__ __forceinline__ void ldsm4(uint32_t* r, uint32_t addr) {
    asm volatile("ldmatrix.sync.aligned.m8n8.x4.shared.b16 {%0,%1,%2,%3}, [%4];"
        : "=r"(r[0]), "=r"(r[1]), "=r"(r[2]), "=r"(r[3]) : "r"(addr));
}
__device__ __forceinline__ void mma16816(float* d, const uint32_t* a, const uint32_t* b) {
    asm volatile("mma.sync.aligned.m16n8k16.row.col.f32.f16.f16.f32 "
        "{%0,%1,%2,%3}, {%4,%5,%6,%7}, {%8,%9}, {%0,%1,%2,%3};"
        : "+f"(d[0]), "+f"(d[1]), "+f"(d[2]), "+f"(d[3])
        : "r"(a[0]), "r"(a[1]), "r"(a[2]), "r"(a[3]), "r"(b[0]), "r"(b[1]));
}
__device__ __forceinline__ float fast_tanh(float x) {
    float e;
    asm("ex2.approx.f32 %0, %1;" : "=f"(e) : "f"(x * 2.8853900817779268f));
    float r;
    asm("rcp.approx.f32 %0, %1;" : "=f"(r) : "f"(e + 1.0f));
    return fmaf(-2.0f, r, 1.0f);
}
__device__ __forceinline__ float fC_cut(float d) {
    return 0.5f * cosf(0.89759790102565521f * d) + 0.5f;
}

// pack W[K][N] fp32 -> B fragments. 14336 threads total.
__global__ void pack_weights(const float* __restrict__ W1, const float* __restrict__ W2,
                             const float* __restrict__ W3, const float* __restrict__ W4,
                             const float* __restrict__ W5, const float* __restrict__ W6) {
    int t = blockIdx.x * 256 + threadIdx.x;
    if (t >= 14336) return;
    int gi = t >> 5, l = t & 31;
    const float* W; uint2* dst; int rel, N, KS;
    if (gi < 128) {
        int L = gi >> 5; rel = gi & 31;
        W = (L == 0) ? W1 : (L == 1) ? W2 : (L == 2) ? W3 : W4;
        dst = g_w14frag + L * 1024; N = 64; KS = 4;
    } else if (gi < 192) {
        rel = gi - 128; W = W5; dst = g_w5frag; N = 128; KS = 4;
    } else {
        rel = gi - 192; W = W6; dst = g_w6frag; N = 256; KS = 8;
    }
    int nt = rel / KS, ks = rel % KS;
    int n = nt * 8 + (l >> 2);
    int k = ks * 16 + (l & 3) * 2;
    __half2 h0 = __floats2half2_rn(W[k * N + n], W[(k + 1) * N + n]);
    __half2 h1 = __floats2half2_rn(W[(k + 8) * N + n], W[(k + 9) * N + n]);
    uint2 u;
    u.x = *reinterpret_cast<uint32_t*>(&h0);
    u.y = *reinterpret_cast<uint32_t*>(&h1);
    dst[rel * 32 + l] = u;
}

__global__ void reduce_out(float* __restrict__ out) {
    int i = blockIdx.x * 512 + threadIdx.x;   // 262144 total
    int center = i >> 8, c = i & 255;
    out[i] = g_part[center * 512 + c] + g_part[center * 512 + 256 + c];
}

// 64->64 mma layer, warp owns 32 rows (2 m16 tiles).
// MODE 0: dst = tanh; MODE 1: dst = tanh + res; MODE 2: in-place (park chunk0)
template<int MODE>
__device__ __forceinline__ void layerG(char* sm8, int srcOff, int dstOff, int resOff,
                                       const uint2* __restrict__ frag,
                                       const float* bias, int lane, int R0)
{
    const int gid = lane >> 2, tig = lane & 3;
    uint32_t aBase = cvta_sh(sm8 + srcOff) + (R0 + (lane & 15)) * 144 + (lane >> 4) * 16;
    uint32_t parked[16];
    __syncwarp();
    #pragma unroll 1
    for (int nch = 0; nch < 2; nch++) {
        float acc[2][4][4];
        #pragma unroll
        for (int nt = 0; nt < 4; nt++) {
            float2 bc = *reinterpret_cast<const float2*>(bias + nch * 32 + nt * 8 + tig * 2);
            #pragma unroll
            for (int m = 0; m < 2; m++) {
                acc[m][nt][0] = bc.x; acc[m][nt][1] = bc.y;
                acc[m][nt][2] = bc.x; acc[m][nt][3] = bc.y;
            }
        }
        #pragma unroll
        for (int ks = 0; ks < 4; ks++) {
            uint32_t a[2][4];
            #pragma unroll
            for (int m = 0; m < 2; m++) ldsm4(a[m], aBase + m * 2304 + ks * 32);
            uint2 bw[4];
            #pragma unroll
            for (int nt = 0; nt < 4; nt++)
                bw[nt] = __ldg(frag + ((nch * 4 + nt) * 4 + ks) * 32 + lane);
            #pragma unroll
            for (int m = 0; m < 2; m++)
                #pragma unroll
                for (int nt = 0; nt < 4; nt++) {
                    uint32_t bb[2] = {bw[nt].x, bw[nt].y};
                    mma16816(acc[m][nt], a[m], bb);
                }
        }
        __syncwarp();
        #pragma unroll
        for (int m = 0; m < 2; m++) {
            #pragma unroll
            for (int nt = 0; nt < 4; nt++) {
                int col = nch * 32 + nt * 8 + tig * 2;
                int row = R0 + m * 16 + gid;
                float v0 = fast_tanh(acc[m][nt][0]);
                float v1 = fast_tanh(acc[m][nt][1]);
                float v2 = fast_tanh(acc[m][nt][2]);
                float v3 = fast_tanh(acc[m][nt][3]);
                if (MODE == 1) {
                    float2 r0 = __half22float2(*(__half2*)(sm8 + resOff + row * 144 + col * 2));
                    float2 r1 = __half22float2(*(__half2*)(sm8 + resOff + (row + 8) * 144 + col * 2));
                    v0 += r0.x; v1 += r0.y; v2 += r1.x; v3 += r1.y;
                }
                __half2 p01 = __floats2half2_rn(v0, v1);
                __half2 p23 = __floats2half2_rn(v2, v3);
                if (MODE == 2 && nch == 0) {
                    parked[(m * 4 + nt) * 2]     = *reinterpret_cast<uint32_t*>(&p01);
                    parked[(m * 4 + nt) * 2 + 1] = *reinterpret_cast<uint32_t*>(&p23);
                } else {
                    *(__half2*)(sm8 + dstOff + row * 144 + col * 2) = p01;
                    *(__half2*)(sm8 + dstOff + (row + 8) * 144 + col * 2) = p23;
                }
            }
        }
    }
    if (MODE == 2) {
        __syncwarp();
        #pragma unroll
        for (int m = 0; m < 2; m++)
            #pragma unroll
            for (int nt = 0; nt < 4; nt++) {
                int col = nt * 8 + tig * 2;
                int row = R0 + m * 16 + gid;
                *(uint32_t*)(sm8 + dstOff + row * 144 + col * 2)       = parked[(m * 4 + nt) * 2];
                *(uint32_t*)(sm8 + dstOff + (row + 8) * 144 + col * 2) = parked[(m * 4 + nt) * 2 + 1];
            }
    }
}

// L5: 64 -> 128, src = P1 (blk2). cols 0-63 -> P0, 64-127 -> P1 (chunk2 parked).
__device__ __forceinline__ void layer5G(char* sm8, const float* bias, int lane, int R0)
{
    const int gid = lane >> 2, tig = lane & 3;
    uint32_t aBase = cvta_sh(sm8 + OFF_P1) + (R0 + (lane & 15)) * 144 + (lane >> 4) * 16;
    uint32_t parked[16];
    __syncwarp();
    #pragma unroll 1
    for (int nch = 0; nch < 4; nch++) {
        float acc[2][4][4];
        #pragma unroll
        for (int nt = 0; nt < 4; nt++) {
            float2 bc = *reinterpret_cast<const float2*>(bias + nch * 32 + nt * 8 + tig * 2);
            #pragma unroll
            for (int m = 0; m < 2; m++) {
                acc[m][nt][0] = bc.x; acc[m][nt][1] = bc.y;
                acc[m][nt][2] = bc.x; acc[m][nt][3] = bc.y;
            }
        }
        #pragma unroll
        for (int ks = 0; ks < 4; ks++) {
            uint32_t a[2][4];
            #pragma unroll
            for (int m = 0; m < 2; m++) ldsm4(a[m], aBase + m * 2304 + ks * 32);
            uint2 bw[4];
            #pragma unroll
            for (int nt = 0; nt < 4; nt++)
                bw[nt] = __ldg(g_w5frag + ((nch * 4 + nt) * 4 + ks) * 32 + lane);
            #pragma unroll
            for (int m = 0; m < 2; m++)
                #pragma unroll
                for (int nt = 0; nt < 4; nt++) {
                    uint32_t bb[2] = {bw[nt].x, bw[nt].y};
                    mma16816(acc[m][nt], a[m], bb);
                }
        }
        int dstOff = (nch < 2) ? OFF_P0 : OFF_P1;
        int dcol = (nch & 1) * 32;
        __syncwarp();
        #pragma unroll
        for (int m = 0; m < 2; m++) {
            #pragma unroll
            for (int nt = 0; nt < 4; nt++) {
                int col = dcol + nt * 8 + tig * 2;
                int row = R0 + m * 16 + gid;
                __half2 p01 = __floats2half2_rn(fast_tanh(acc[m][nt][0]), fast_tanh(acc[m][nt][1]));
                __half2 p23 = __floats2half2_rn(fast_tanh(acc[m][nt][2]), fast_tanh(acc[m][nt][3]));
                if (nch == 2) {
                    parked[(m * 4 + nt) * 2]     = *reinterpret_cast<uint32_t*>(&p01);
                    parked[(m * 4 + nt) * 2 + 1] = *reinterpret_cast<uint32_t*>(&p23);
                } else {
                    *(__half2*)(sm8 + dstOff + row * 144 + col * 2) = p01;
                    *(__half2*)(sm8 + dstOff + (row + 8) * 144 + col * 2) = p23;
                }
            }
        }
    }
    __syncwarp();
    #pragma unroll
    for (int m = 0; m < 2; m++)
        #pragma unroll
        for (int nt = 0; nt < 4; nt++) {
            int col = nt * 8 + tig * 2;
            int row = R0 + m * 16 + gid;
            *(uint32_t*)(sm8 + OFF_P1 + row * 144 + col * 2)       = parked[(m * 4 + nt) * 2];
            *(uint32_t*)(sm8 + OFF_P1 + (row + 8) * 144 + col * 2) = parked[(m * 4 + nt) * 2 + 1];
        }
}

// L6: 128 -> 256, epilogue tanh*smooth + reduce over warp rows -> AEV
__device__ __forceinline__ void layer6G(char* sm8, const float* bias, int lane, int R0, int wid)
{
    const int gid = lane >> 2, tig = lane & 3;
    uint32_t aBase0 = cvta_sh(sm8 + OFF_P0) + (R0 + (lane & 15)) * 144 + (lane >> 4) * 16;
    uint32_t aBase1 = cvta_sh(sm8 + OFF_P1) + (R0 + (lane & 15)) * 144 + (lane >> 4) * 16;
    const float* smoothF = (const float*)(sm8 + OFF_SMOOTH);
    float* aev = (float*)(sm8 + OFF_AEV) + wid * 256;
    float s[2][2];
    __syncwarp();
    #pragma unroll
    for (int m = 0; m < 2; m++) {
        s[m][0] = smoothF[R0 + m * 16 + gid];
        s[m][1] = smoothF[R0 + m * 16 + gid + 8];
    }
    #pragma unroll 1
    for (int nch = 0; nch < 8; nch++) {
        float acc[2][4][4];
        #pragma unroll
        for (int nt = 0; nt < 4; nt++) {
            float2 bc = *reinterpret_cast<const float2*>(bias + nch * 32 + nt * 8 + tig * 2);
            #pragma unroll
            for (int m = 0; m < 2; m++) {
                acc[m][nt][0] = bc.x; acc[m][nt][1] = bc.y;
                acc[m][nt][2] = bc.x; acc[m][nt][3] = bc.y;
            }
        }
        #pragma unroll
        for (int ks = 0; ks < 8; ks++) {
            uint32_t ab = (ks < 4) ? (aBase0 + ks * 32) : (aBase1 + (ks - 4) * 32);
            uint32_t a[2][4];
            #pragma unroll
            for (int m = 0; m < 2; m++) ldsm4(a[m], ab + m * 2304);
            uint2 bw[4];
            #pragma unroll
            for (int nt = 0; nt < 4; nt++)
                bw[nt] = __ldg(g_w6frag + ((nch * 4 + nt) * 8 + ks) * 32 + lane);
            #pragma unroll
            for (int m = 0; m < 2; m++)
                #pragma unroll
                for (int nt = 0; nt < 4; nt++) {
                    uint32_t bb[2] = {bw[nt].x, bw[nt].y};
                    mma16816(acc[m][nt], a[m], bb);
                }
        }
        float t0[4] = {0.f, 0.f, 0.f, 0.f}, t1[4] = {0.f, 0.f, 0.f, 0.f};
        #pragma unroll
        for (int m = 0; m < 2; m++)
            #pragma unroll
            for (int nt = 0; nt < 4; nt++) {
                t0[nt] += fast_tanh(acc[m][nt][0]) * s[m][0] + fast_tanh(acc[m][nt][2]) * s[m][1];
                t1[nt] += fast_tanh(acc[m][nt][1]) * s[m][0] + fast_tanh(acc[m][nt][3]) * s[m][1];
            }
        #pragma unroll
        for (int nt = 0; nt < 4; nt++) {
            #pragma unroll
            for (int sh = 4; sh < 32; sh <<= 1) {
                t0[nt] += __shfl_xor_sync(0xffffffffu, t0[nt], sh);
                t1[nt] += __shfl_xor_sync(0xffffffffu, t1[nt], sh);
            }
        }
        if (lane < 4) {
            #pragma unroll
            for (int nt = 0; nt < 4; nt++) {
                int col = nch * 32 + nt * 8 + lane * 2;
                aev[col] = t0[nt];
                aev[col + 1] = t1[nt];
            }
        }
    }
}

__global__ void __launch_bounds__(TPB, 2)
Obiwan_84335977825044_kernel(
    const float* __restrict__ gD, const float* __restrict__ gZ,
    const float* __restrict__ W0, const float* __restrict__ b0,
    const float* __restrict__ b1, const float* __restrict__ b2,
    const float* __restrict__ b3, const float* __restrict__ b4,
    const float* __restrict__ b5, const float* __restrict__ b6)
{
    extern __shared__ char sm8[];
    const int tid  = threadIdx.x;
    const int lane = tid & 31;
    const int wid  = tid >> 5;
    const int bidx = blockIdx.x;
    const int center = bidx >> 1;
    const int half = bidx & 1;
    const int b    = center >> 5;
    const int ictr = center & 31;

    float* W0F   = (float*)(sm8 + OFF_W0);
    float* biasF = (float*)(sm8 + OFF_BIAS);
    float* smF   = (float*)(sm8 + OFF_SMOOTH);
    float* sDF   = (float*)(sm8 + OFF_D);
    float* sZF   = (float*)(sm8 + OFF_Z);

    // ---- staging (small) ----
    for (int i = tid; i < 1024; i += TPB) sDF[i] = gD[b * 1024 + i];
    if (tid < 32) sZF[tid] = gZ[b * 32 + tid];
    for (int i = tid; i < 576; i += TPB) W0F[i] = W0[i];
    if (tid < 64) {
        biasF[tid] = b0[tid]; biasF[64 + tid] = b1[tid]; biasF[128 + tid] = b2[tid];
        biasF[192 + tid] = b3[tid]; biasF[256 + tid] = b4[tid];
    }
    if (tid < 128) biasF[320 + tid] = b5[tid];
    for (int i = tid; i < 256; i += TPB) biasF[448 + i] = b6[i];
    __syncthreads();

    // ---- L0 (scalar fp32): one row per thread ----
    {
        int r = half * 256 + tid;
        bool valid = (r < 465);
        int rem = valid ? r : 0;
        int a = 0;
        while (rem >= 30 - a) { rem -= 30 - a; a++; }
        int bb2 = a + 1 + rem;
        int j = a + (a >= ictr);
        int k = bb2 + (bb2 >= ictr);

        float Rij = sDF[ictr * 32 + j];
        float Rik = sDF[ictr * 32 + k];
        float Rjk = sDF[j * 32 + k];
        float zi = sZF[ictr], zj = sZF[j], zk = sZF[k];

        float rij2 = Rij * Rij, rik2 = Rik * Rik, rjk2 = Rjk * Rjk;
        float ci = (rij2 + rik2 - rjk2) / fmaxf(2.f * Rij * Rik, 1e-10f);
        float cj = (rij2 + rjk2 - rik2) / fmaxf(2.f * Rij * Rjk, 1e-10f);
        float ck = (rik2 + rjk2 - rij2) / fmaxf(2.f * Rik * Rjk, 1e-10f);

        float g0 = Rij + Rik + Rjk;
        float g1 = Rij * Rik + Rij * Rjk + Rik * Rjk;
        float g2 = Rij * Rik * Rjk;

        float h0 = zi + zj + zk;
        float h1 = ci + cj + ck;
        float h2 = zi * (zj + zk) + zj * zk - ci * (cj + ck) - cj * ck;
        float h3 = zi * (cj + ck) + ci * (zj + zk) + zj * ck + cj * zk;
        float h4 = zi * (zj * zk - cj * ck) - ci * (zj * ck + cj * zk);
        float h5 = zi * (zj * ck + cj * zk) + ci * (zj * zk - cj * ck);

        float ign = 1.f / (sqrtf(g0 * g0 + g1 * g1 + g2 * g2) + 1e-7f);
        float icn = 1.f / (sqrtf(h0 * h0 + h1 * h1 + h2 * h2 + h3 * h3 + h4 * h4 + h5 * h5) + 1e-7f);

        float smooth = 0.f;
        if (valid && Rij < 3.5f && Rik < 3.5f) smooth = fC_cut(Rij) * fC_cut(Rik);
        smF[tid] = smooth;

        float in9[9];
        in9[0] = g0 * ign; in9[1] = g1 * ign; in9[2] = g2 * ign;
        in9[3] = h0 * icn; in9[4] = h1 * icn; in9[5] = h2 * icn;
        in9[6] = h3 * icn; in9[7] = h4 * icn; in9[8] = h5 * icn;
        if (!valid) {
            #pragma unroll
            for (int q = 0; q < 9; q++) in9[q] = 0.f;
        }

        float acc[64];
        #pragma unroll
        for (int o = 0; o < 64; o += 4) {
            float4 bbv = *reinterpret_cast<const float4*>(biasF + o);
            acc[o] = bbv.x; acc[o + 1] = bbv.y; acc[o + 2] = bbv.z; acc[o + 3] = bbv.w;
        }
        #pragma unroll 1
        for (int kk = 0; kk < 9; kk++) {
            float xk = in9[kk];
            const float4* w4 = reinterpret_cast<const float4*>(W0F + kk * 64);
            #pragma unroll
            for (int o = 0; o < 64; o += 4) {
                float4 w = w4[o >> 2];
                acc[o]     = fmaf(xk, w.x, acc[o]);
                acc[o + 1] = fmaf(xk, w.y, acc[o + 1]);
                acc[o + 2] = fmaf(xk, w.z, acc[o + 2]);
                acc[o + 3] = fmaf(xk, w.w, acc[o + 3]);
            }
        }
        #pragma unroll
        for (int o = 0; o < 64; o += 2) {
            __half2 h = __floats2half2_rn(fast_tanh(acc[o]), fast_tanh(acc[o + 1]));
            *(__half2*)(sm8 + OFF_P0 + tid * 144 + o * 2) = h;
        }
    }
    __syncthreads();

    // ---- warp-tiled MLP: each warp owns rows [32*wid, 32*wid+32) ----
    const int R0 = wid * 32;
    layerG<1>(sm8, OFF_P0, OFF_P1, OFF_P0, g_w14frag,        biasF + 64,  lane, R0); // blk1
    layerG<0>(sm8, OFF_P1, OFF_P0, 0,      g_w14frag + 1024, biasF + 128, lane, R0);
    layerG<2>(sm8, OFF_P0, OFF_P0, 0,      g_w14frag + 2048, biasF + 192, lane, R0);
    layerG<1>(sm8, OFF_P0, OFF_P1, OFF_P1, g_w14frag + 3072, biasF + 256, lane, R0); // blk2
    layer5G(sm8, biasF + 320, lane, R0);                                             // blk3
    layer6G(sm8, biasF + 448, lane, R0, wid);

    // ---- block reduce, write partial ----
    __syncthreads();
    float* aevF = (float*)(sm8 + OFF_AEV);
    float sum = 0.f;
    #pragma unroll
    for (int w = 0; w < 8; ++w) sum += aevF[w * 256 + tid];
    g_part[bidx * 256 + tid] = sum;
}

extern "C" void kernel_launch(void* const* d_in, const int* in_sizes, int n_in,
                              void* d_out, int out_size) {
    const float* D  = (const float*)d_in[0];
    const float* Z  = (const float*)d_in[1];
    const float* W0 = (const float*)d_in[2];  const float* b0 = (const float*)d_in[3];
    const float* W1 = (const float*)d_in[4];  const float* b1 = (const float*)d_in[5];
    const float* W2 = (const float*)d_in[6];  const float* b2 = (const float*)d_in[7];
    const float* W3 = (const float*)d_in[8];  const float* b3 = (const float*)d_in[9];
    const float* W4 = (const float*)d_in[10]; const float* b4 = (const float*)d_in[11];
    const float* W5 = (const float*)d_in[12]; const float* b5 = (const float*)d_in[13];
    const float* W6 = (const float*)d_in[14]; const float* b6 = (const float*)d_in[15];

    pack_weights<<<56, 256>>>(W1, W2, W3, W4, W5, W6);

    cudaFuncSetAttribute(Obiwan_84335977825044_kernel,
                         cudaFuncAttributeMaxDynamicSharedMemorySize, SMEM_BYTES);
    Obiwan_84335977825044_kernel<<<2048, TPB, SMEM_BYTES>>>(
        D, Z, W0, b0, b1, b2, b3, b4, b5, b6);

    reduce_out<<<512, 512>>>((float*)d_out);
}

// round 6
// speedup vs baseline: 15.5354x; 1.2356x over previous
#include <cuda_runtime.h>
#include <cuda_fp16.h>
#include <stdint.h>

#define TPB 256

// ---- dynamic smem layout (byte offsets) ----
#define OFF_P0     0         // plane0 fp16 [256][72]
#define OFF_P1     36864     // plane1 fp16 [256][72]
#define OFF_D      73728     // 1024 fp32
#define OFF_Z      77824     // 32 fp32
#define OFF_SMOOTH 77952     // 256 fp32
#define OFF_BIAS   78976     // 704 fp32: b0|b1|b2|b3|b4|b5|b6
#define OFF_AEV    81792     // 8 warps * 256 fp32
#define OFF_W0     89984     // 576 fp32
#define SMEM_BYTES 92288

// weight fragments (B operand of m16n8k16), packed once per launch
__device__ uint2 g_w14frag[4 * 1024];   // W1..W4: 8 ntiles * 4 ksteps * 32 lanes
__device__ uint2 g_w5frag[2048];        // W5: 16 ntiles * 4 ksteps * 32
__device__ uint2 g_w6frag[8192];        // W6: 32 ntiles * 8 ksteps * 32
__device__ float g_part[2048 * 256];    // per-block partial AEV

__device__ __forceinline__ uint32_t cvta_sh(const void* p) {
    return (uint32_t)__cvta_generic_to_shared(p);
}
__device__ __forceinline__ void ldsm4(uint32_t* r, uint32_t addr) {
    asm volatile("ldmatrix.sync.aligned.m8n8.x4.shared.b16 {%0,%1,%2,%3}, [%4];"
        : "=r"(r[0]), "=r"(r[1]), "=r"(r[2]), "=r"(r[3]) : "r"(addr));
}
__device__ __forceinline__ void mma16816(float* d, const uint32_t* a, const uint32_t* b) {
    asm volatile("mma.sync.aligned.m16n8k16.row.col.f32.f16.f16.f32 "
        "{%0,%1,%2,%3}, {%4,%5,%6,%7}, {%8,%9}, {%0,%1,%2,%3};"
        : "+f"(d[0]), "+f"(d[1]), "+f"(d[2]), "+f"(d[3])
        : "r"(a[0]), "r"(a[1]), "r"(a[2]), "r"(a[3]), "r"(b[0]), "r"(b[1]));
}
// 1-MUFU hardware tanh (max rel err ~2^-11, same order as fp16 storage rounding)
__device__ __forceinline__ float tanh_hw(float x) {
    float y;
    asm("tanh.approx.f32 %0, %1;" : "=f"(y) : "f"(x));
    return y;
}
// precise 2-MUFU tanh (rel err ~1e-6) — used only in the final layer epilogue
__device__ __forceinline__ float fast_tanh(float x) {
    float e;
    asm("ex2.approx.f32 %0, %1;" : "=f"(e) : "f"(x * 2.8853900817779268f));
    float r;
    asm("rcp.approx.f32 %0, %1;" : "=f"(r) : "f"(e + 1.0f));
    return fmaf(-2.0f, r, 1.0f);
}
__device__ __forceinline__ float fC_cut(float d) {
    return 0.5f * cosf(0.89759790102565521f * d) + 0.5f;
}

// pack W[K][N] fp32 -> B fragments. 14336 threads total.
__global__ void pack_weights(const float* __restrict__ W1, const float* __restrict__ W2,
                             const float* __restrict__ W3, const float* __restrict__ W4,
                             const float* __restrict__ W5, const float* __restrict__ W6) {
    int t = blockIdx.x * 256 + threadIdx.x;
    if (t >= 14336) return;
    int gi = t >> 5, l = t & 31;
    const float* W; uint2* dst; int rel, N, KS;
    if (gi < 128) {
        int L = gi >> 5; rel = gi & 31;
        W = (L == 0) ? W1 : (L == 1) ? W2 : (L == 2) ? W3 : W4;
        dst = g_w14frag + L * 1024; N = 64; KS = 4;
    } else if (gi < 192) {
        rel = gi - 128; W = W5; dst = g_w5frag; N = 128; KS = 4;
    } else {
        rel = gi - 192; W = W6; dst = g_w6frag; N = 256; KS = 8;
    }
    int nt = rel / KS, ks = rel % KS;
    int n = nt * 8 + (l >> 2);
    int k = ks * 16 + (l & 3) * 2;
    __half2 h0 = __floats2half2_rn(W[k * N + n], W[(k + 1) * N + n]);
    __half2 h1 = __floats2half2_rn(W[(k + 8) * N + n], W[(k + 9) * N + n]);
    uint2 u;
    u.x = *reinterpret_cast<uint32_t*>(&h0);
    u.y = *reinterpret_cast<uint32_t*>(&h1);
    dst[rel * 32 + l] = u;
}

__global__ void reduce_out(float* __restrict__ out) {
    int i = blockIdx.x * 512 + threadIdx.x;   // 262144 total
    int center = i >> 8, c = i & 255;
    out[i] = g_part[center * 512 + c] + g_part[center * 512 + 256 + c];
}

// 64->64 mma layer, warp owns 32 rows (2 m16 tiles).
// MODE 0: dst = tanh; MODE 1: dst = tanh + res; MODE 2: in-place (park chunk0)
template<int MODE>
__device__ __forceinline__ void layerG(char* sm8, int srcOff, int dstOff, int resOff,
                                       const uint2* __restrict__ frag,
                                       const float* bias, int lane, int R0)
{
    const int gid = lane >> 2, tig = lane & 3;
    uint32_t aBase = cvta_sh(sm8 + srcOff) + (R0 + (lane & 15)) * 144 + (lane >> 4) * 16;
    uint32_t parked[16];
    __syncwarp();
    #pragma unroll 1
    for (int nch = 0; nch < 2; nch++) {
        float acc[2][4][4];
        #pragma unroll
        for (int nt = 0; nt < 4; nt++) {
            float2 bc = *reinterpret_cast<const float2*>(bias + nch * 32 + nt * 8 + tig * 2);
            #pragma unroll
            for (int m = 0; m < 2; m++) {
                acc[m][nt][0] = bc.x; acc[m][nt][1] = bc.y;
                acc[m][nt][2] = bc.x; acc[m][nt][3] = bc.y;
            }
        }
        #pragma unroll
        for (int ks = 0; ks < 4; ks++) {
            uint32_t a[2][4];
            #pragma unroll
            for (int m = 0; m < 2; m++) ldsm4(a[m], aBase + m * 2304 + ks * 32);
            uint2 bw[4];
            #pragma unroll
            for (int nt = 0; nt < 4; nt++)
                bw[nt] = __ldg(frag + ((nch * 4 + nt) * 4 + ks) * 32 + lane);
            #pragma unroll
            for (int m = 0; m < 2; m++)
                #pragma unroll
                for (int nt = 0; nt < 4; nt++) {
                    uint32_t bb[2] = {bw[nt].x, bw[nt].y};
                    mma16816(acc[m][nt], a[m], bb);
                }
        }
        __syncwarp();
        #pragma unroll
        for (int m = 0; m < 2; m++) {
            #pragma unroll
            for (int nt = 0; nt < 4; nt++) {
                int col = nch * 32 + nt * 8 + tig * 2;
                int row = R0 + m * 16 + gid;
                float v0 = tanh_hw(acc[m][nt][0]);
                float v1 = tanh_hw(acc[m][nt][1]);
                float v2 = tanh_hw(acc[m][nt][2]);
                float v3 = tanh_hw(acc[m][nt][3]);
                if (MODE == 1) {
                    float2 r0 = __half22float2(*(__half2*)(sm8 + resOff + row * 144 + col * 2));
                    float2 r1 = __half22float2(*(__half2*)(sm8 + resOff + (row + 8) * 144 + col * 2));
                    v0 += r0.x; v1 += r0.y; v2 += r1.x; v3 += r1.y;
                }
                __half2 p01 = __floats2half2_rn(v0, v1);
                __half2 p23 = __floats2half2_rn(v2, v3);
                if (MODE == 2 && nch == 0) {
                    parked[(m * 4 + nt) * 2]     = *reinterpret_cast<uint32_t*>(&p01);
                    parked[(m * 4 + nt) * 2 + 1] = *reinterpret_cast<uint32_t*>(&p23);
                } else {
                    *(__half2*)(sm8 + dstOff + row * 144 + col * 2) = p01;
                    *(__half2*)(sm8 + dstOff + (row + 8) * 144 + col * 2) = p23;
                }
            }
        }
    }
    if (MODE == 2) {
        __syncwarp();
        #pragma unroll
        for (int m = 0; m < 2; m++)
            #pragma unroll
            for (int nt = 0; nt < 4; nt++) {
                int col = nt * 8 + tig * 2;
                int row = R0 + m * 16 + gid;
                *(uint32_t*)(sm8 + dstOff + row * 144 + col * 2)       = parked[(m * 4 + nt) * 2];
                *(uint32_t*)(sm8 + dstOff + (row + 8) * 144 + col * 2) = parked[(m * 4 + nt) * 2 + 1];
            }
    }
}

// L5: 64 -> 128, src = P1 (blk2). cols 0-63 -> P0, 64-127 -> P1 (chunk2 parked).
__device__ __forceinline__ void layer5G(char* sm8, const float* bias, int lane, int R0)
{
    const int gid = lane >> 2, tig = lane & 3;
    uint32_t aBase = cvta_sh(sm8 + OFF_P1) + (R0 + (lane & 15)) * 144 + (lane >> 4) * 16;
    uint32_t parked[16];
    __syncwarp();
    #pragma unroll 1
    for (int nch = 0; nch < 4; nch++) {
        float acc[2][4][4];
        #pragma unroll
        for (int nt = 0; nt < 4; nt++) {
            float2 bc = *reinterpret_cast<const float2*>(bias + nch * 32 + nt * 8 + tig * 2);
            #pragma unroll
            for (int m = 0; m < 2; m++) {
                acc[m][nt][0] = bc.x; acc[m][nt][1] = bc.y;
                acc[m][nt][2] = bc.x; acc[m][nt][3] = bc.y;
            }
        }
        #pragma unroll
        for (int ks = 0; ks < 4; ks++) {
            uint32_t a[2][4];
            #pragma unroll
            for (int m = 0; m < 2; m++) ldsm4(a[m], aBase + m * 2304 + ks * 32);
            uint2 bw[4];
            #pragma unroll
            for (int nt = 0; nt < 4; nt++)
                bw[nt] = __ldg(g_w5frag + ((nch * 4 + nt) * 4 + ks) * 32 + lane);
            #pragma unroll
            for (int m = 0; m < 2; m++)
                #pragma unroll
                for (int nt = 0; nt < 4; nt++) {
                    uint32_t bb[2] = {bw[nt].x, bw[nt].y};
                    mma16816(acc[m][nt], a[m], bb);
                }
        }
        int dstOff = (nch < 2) ? OFF_P0 : OFF_P1;
        int dcol = (nch & 1) * 32;
        __syncwarp();
        #pragma unroll
        for (int m = 0; m < 2; m++) {
            #pragma unroll
            for (int nt = 0; nt < 4; nt++) {
                int col = dcol + nt * 8 + tig * 2;
                int row = R0 + m * 16 + gid;
                __half2 p01 = __floats2half2_rn(tanh_hw(acc[m][nt][0]), tanh_hw(acc[m][nt][1]));
                __half2 p23 = __floats2half2_rn(tanh_hw(acc[m][nt][2]), tanh_hw(acc[m][nt][3]));
                if (nch == 2) {
                    parked[(m * 4 + nt) * 2]     = *reinterpret_cast<uint32_t*>(&p01);
                    parked[(m * 4 + nt) * 2 + 1] = *reinterpret_cast<uint32_t*>(&p23);
                } else {
                    *(__half2*)(sm8 + dstOff + row * 144 + col * 2) = p01;
                    *(__half2*)(sm8 + dstOff + (row + 8) * 144 + col * 2) = p23;
                }
            }
        }
    }
    __syncwarp();
    #pragma unroll
    for (int m = 0; m < 2; m++)
        #pragma unroll
        for (int nt = 0; nt < 4; nt++) {
            int col = nt * 8 + tig * 2;
            int row = R0 + m * 16 + gid;
            *(uint32_t*)(sm8 + OFF_P1 + row * 144 + col * 2)       = parked[(m * 4 + nt) * 2];
            *(uint32_t*)(sm8 + OFF_P1 + (row + 8) * 144 + col * 2) = parked[(m * 4 + nt) * 2 + 1];
        }
}

// L6: 128 -> 256, epilogue precise tanh*smooth + reduce over warp rows -> AEV
__device__ __forceinline__ void layer6G(char* sm8, const float* bias, int lane, int R0, int wid)
{
    const int gid = lane >> 2, tig = lane & 3;
    uint32_t aBase0 = cvta_sh(sm8 + OFF_P0) + (R0 + (lane & 15)) * 144 + (lane >> 4) * 16;
    uint32_t aBase1 = cvta_sh(sm8 + OFF_P1) + (R0 + (lane & 15)) * 144 + (lane >> 4) * 16;
    const float* smoothF = (const float*)(sm8 + OFF_SMOOTH);
    float* aev = (float*)(sm8 + OFF_AEV) + wid * 256;
    float s[2][2];
    __syncwarp();
    #pragma unroll
    for (int m = 0; m < 2; m++) {
        s[m][0] = smoothF[R0 + m * 16 + gid];
        s[m][1] = smoothF[R0 + m * 16 + gid + 8];
    }
    #pragma unroll 1
    for (int nch = 0; nch < 8; nch++) {
        float acc[2][4][4];
        #pragma unroll
        for (int nt = 0; nt < 4; nt++) {
            float2 bc = *reinterpret_cast<const float2*>(bias + nch * 32 + nt * 8 + tig * 2);
            #pragma unroll
            for (int m = 0; m < 2; m++) {
                acc[m][nt][0] = bc.x; acc[m][nt][1] = bc.y;
                acc[m][nt][2] = bc.x; acc[m][nt][3] = bc.y;
            }
        }
        #pragma unroll
        for (int ks = 0; ks < 8; ks++) {
            uint32_t ab = (ks < 4) ? (aBase0 + ks * 32) : (aBase1 + (ks - 4) * 32);
            uint32_t a[2][4];
            #pragma unroll
            for (int m = 0; m < 2; m++) ldsm4(a[m], ab + m * 2304);
            uint2 bw[4];
            #pragma unroll
            for (int nt = 0; nt < 4; nt++)
                bw[nt] = __ldg(g_w6frag + ((nch * 4 + nt) * 8 + ks) * 32 + lane);
            #pragma unroll
            for (int m = 0; m < 2; m++)
                #pragma unroll
                for (int nt = 0; nt < 4; nt++) {
                    uint32_t bb[2] = {bw[nt].x, bw[nt].y};
                    mma16816(acc[m][nt], a[m], bb);
                }
        }
        float t0[4] = {0.f, 0.f, 0.f, 0.f}, t1[4] = {0.f, 0.f, 0.f, 0.f};
        #pragma unroll
        for (int m = 0; m < 2; m++)
            #pragma unroll
            for (int nt = 0; nt < 4; nt++) {
                t0[nt] += fast_tanh(acc[m][nt][0]) * s[m][0] + fast_tanh(acc[m][nt][2]) * s[m][1];
                t1[nt] += fast_tanh(acc[m][nt][1]) * s[m][0] + fast_tanh(acc[m][nt][3]) * s[m][1];
            }
        #pragma unroll
        for (int nt = 0; nt < 4; nt++) {
            #pragma unroll
            for (int sh = 4; sh < 32; sh <<= 1) {
                t0[nt] += __shfl_xor_sync(0xffffffffu, t0[nt], sh);
                t1[nt] += __shfl_xor_sync(0xffffffffu, t1[nt], sh);
            }
        }
        if (lane < 4) {
            #pragma unroll
            for (int nt = 0; nt < 4; nt++) {
                int col = nch * 32 + nt * 8 + lane * 2;
                aev[col] = t0[nt];
                aev[col + 1] = t1[nt];
            }
        }
    }
}

__global__ void __launch_bounds__(TPB, 2)
Obiwan_84335977825044_kernel(
    const float* __restrict__ gD, const float* __restrict__ gZ,
    const float* __restrict__ W0, const float* __restrict__ b0,
    const float* __restrict__ b1, const float* __restrict__ b2,
    const float* __restrict__ b3, const float* __restrict__ b4,
    const float* __restrict__ b5, const float* __restrict__ b6)
{
    extern __shared__ char sm8[];
    const int tid  = threadIdx.x;
    const int lane = tid & 31;
    const int wid  = tid >> 5;
    const int bidx = blockIdx.x;
    const int center = bidx >> 1;
    const int half = bidx & 1;
    const int b    = center >> 5;
    const int ictr = center & 31;

    float* W0F   = (float*)(sm8 + OFF_W0);
    float* biasF = (float*)(sm8 + OFF_BIAS);
    float* smF   = (float*)(sm8 + OFF_SMOOTH);
    float* sDF   = (float*)(sm8 + OFF_D);
    float* sZF   = (float*)(sm8 + OFF_Z);

    // ---- staging (small) ----
    for (int i = tid; i < 1024; i += TPB) sDF[i] = gD[b * 1024 + i];
    if (tid < 32) sZF[tid] = gZ[b * 32 + tid];
    for (int i = tid; i < 576; i += TPB) W0F[i] = W0[i];
    if (tid < 64) {
        biasF[tid] = b0[tid]; biasF[64 + tid] = b1[tid]; biasF[128 + tid] = b2[tid];
        biasF[192 + tid] = b3[tid]; biasF[256 + tid] = b4[tid];
    }
    if (tid < 128) biasF[320 + tid] = b5[tid];
    for (int i = tid; i < 256; i += TPB) biasF[448 + i] = b6[i];
    __syncthreads();

    // ---- L0 (scalar fp32): one row per thread ----
    {
        int r = half * 256 + tid;
        bool valid = (r < 465);
        int rem = valid ? r : 0;
        int a = 0;
        while (rem >= 30 - a) { rem -= 30 - a; a++; }
        int bb2 = a + 1 + rem;
        int j = a + (a >= ictr);
        int k = bb2 + (bb2 >= ictr);

        float Rij = sDF[ictr * 32 + j];
        float Rik = sDF[ictr * 32 + k];
        float Rjk = sDF[j * 32 + k];
        float zi = sZF[ictr], zj = sZF[j], zk = sZF[k];

        float rij2 = Rij * Rij, rik2 = Rik * Rik, rjk2 = Rjk * Rjk;
        float ci = (rij2 + rik2 - rjk2) / fmaxf(2.f * Rij * Rik, 1e-10f);
        float cj = (rij2 + rjk2 - rik2) / fmaxf(2.f * Rij * Rjk, 1e-10f);
        float ck = (rik2 + rjk2 - rij2) / fmaxf(2.f * Rik * Rjk, 1e-10f);

        float g0 = Rij + Rik + Rjk;
        float g1 = Rij * Rik + Rij * Rjk + Rik * Rjk;
        float g2 = Rij * Rik * Rjk;

        float h0 = zi + zj + zk;
        float h1 = ci + cj + ck;
        float h2 = zi * (zj + zk) + zj * zk - ci * (cj + ck) - cj * ck;
        float h3 = zi * (cj + ck) + ci * (zj + zk) + zj * ck + cj * zk;
        float h4 = zi * (zj * zk - cj * ck) - ci * (zj * ck + cj * zk);
        float h5 = zi * (zj * ck + cj * zk) + ci * (zj * zk - cj * ck);

        float ign = 1.f / (sqrtf(g0 * g0 + g1 * g1 + g2 * g2) + 1e-7f);
        float icn = 1.f / (sqrtf(h0 * h0 + h1 * h1 + h2 * h2 + h3 * h3 + h4 * h4 + h5 * h5) + 1e-7f);

        float smooth = 0.f;
        if (valid && Rij < 3.5f && Rik < 3.5f) smooth = fC_cut(Rij) * fC_cut(Rik);
        smF[tid] = smooth;

        float in9[9];
        in9[0] = g0 * ign; in9[1] = g1 * ign; in9[2] = g2 * ign;
        in9[3] = h0 * icn; in9[4] = h1 * icn; in9[5] = h2 * icn;
        in9[6] = h3 * icn; in9[7] = h4 * icn; in9[8] = h5 * icn;
        if (!valid) {
            #pragma unroll
            for (int q = 0; q < 9; q++) in9[q] = 0.f;
        }

        float acc[64];
        #pragma unroll
        for (int o = 0; o < 64; o += 4) {
            float4 bbv = *reinterpret_cast<const float4*>(biasF + o);
            acc[o] = bbv.x; acc[o + 1] = bbv.y; acc[o + 2] = bbv.z; acc[o + 3] = bbv.w;
        }
        #pragma unroll 1
        for (int kk = 0; kk < 9; kk++) {
            float xk = in9[kk];
            const float4* w4 = reinterpret_cast<const float4*>(W0F + kk * 64);
            #pragma unroll
            for (int o = 0; o < 64; o += 4) {
                float4 w = w4[o >> 2];
                acc[o]     = fmaf(xk, w.x, acc[o]);
                acc[o + 1] = fmaf(xk, w.y, acc[o + 1]);
                acc[o + 2] = fmaf(xk, w.z, acc[o + 2]);
                acc[o + 3] = fmaf(xk, w.w, acc[o + 3]);
            }
        }
        #pragma unroll
        for (int o = 0; o < 64; o += 2) {
            __half2 h = __floats2half2_rn(tanh_hw(acc[o]), tanh_hw(acc[o + 1]));
            *(__half2*)(sm8 + OFF_P0 + tid * 144 + o * 2) = h;
        }
    }
    __syncthreads();

    // ---- warp-tiled MLP: each warp owns rows [32*wid, 32*wid+32) ----
    const int R0 = wid * 32;
    layerG<1>(sm8, OFF_P0, OFF_P1, OFF_P0, g_w14frag,        biasF + 64,  lane, R0); // blk1
    layerG<0>(sm8, OFF_P1, OFF_P0, 0,      g_w14frag + 1024, biasF + 128, lane, R0);
    layerG<2>(sm8, OFF_P0, OFF_P0, 0,      g_w14frag + 2048, biasF + 192, lane, R0);
    layerG<1>(sm8, OFF_P0, OFF_P1, OFF_P1, g_w14frag + 3072, biasF + 256, lane, R0); // blk2
    layer5G(sm8, biasF + 320, lane, R0);                                             // blk3
    layer6G(sm8, biasF + 448, lane, R0, wid);

    // ---- block reduce, write partial ----
    __syncthreads();
    float* aevF = (float*)(sm8 + OFF_AEV);
    float sum = 0.f;
    #pragma unroll
    for (int w = 0; w < 8; ++w) sum += aevF[w * 256 + tid];
    g_part[bidx * 256 + tid] = sum;
}

extern "C" void kernel_launch(void* const* d_in, const int* in_sizes, int n_in,
                              void* d_out, int out_size) {
    const float* D  = (const float*)d_in[0];
    const float* Z  = (const float*)d_in[1];
    const float* W0 = (const float*)d_in[2];  const float* b0 = (const float*)d_in[3];
    const float* W1 = (const float*)d_in[4];  const float* b1 = (const float*)d_in[5];
    const float* W2 = (const float*)d_in[6];  const float* b2 = (const float*)d_in[7];
    const float* W3 = (const float*)d_in[8];  const float* b3 = (const float*)d_in[9];
    const float* W4 = (const float*)d_in[10]; const float* b4 = (const float*)d_in[11];
    const float* W5 = (const float*)d_in[12]; const float* b5 = (const float*)d_in[13];
    const float* W6 = (const float*)d_in[14]; const float* b6 = (const float*)d_in[15];

    pack_weights<<<56, 256>>>(W1, W2, W3, W4, W5, W6);

    cudaFuncSetAttribute(Obiwan_84335977825044_kernel,
                         cudaFuncAttributeMaxDynamicSharedMemorySize, SMEM_BYTES);
    Obiwan_84335977825044_kernel<<<2048, TPB, SMEM_BYTES>>>(
        D, Z, W0, b0, b1, b2, b3, b4, b5, b6);

    reduce_out<<<512, 512>>>((float*)d_out);
}

// round 7
// speedup vs baseline: 18.1442x; 1.1679x over previous
#include <cuda_runtime.h>
#include <cuda_fp16.h>
#include <stdint.h>

#define TPB 256

// ---- dynamic smem layout (byte offsets) ----
#define OFF_P0     0         // plane0 fp16 [256][72]
#define OFF_P1     36864     // plane1 fp16 [256][72]
#define OFF_D      73728     // 1024 fp32
#define OFF_Z      77824     // 32 fp32
#define OFF_SMOOTH 77952     // 256 fp32
#define OFF_BIAS   78976     // 704 fp32: b0|b1|b2|b3|b4|b5|b6
#define OFF_AEV    81792     // 8 warps * 256 fp32
#define OFF_W0     89984     // 576 fp32
#define SMEM_BYTES 92288

// weight fragments (B operand of m16n8k16), packed once per launch
__device__ uint2 g_w14frag[4 * 1024];   // W1..W4: 8 ntiles * 4 ksteps * 32 lanes
__device__ uint2 g_w5frag[2048];        // W5: 16 ntiles * 4 ksteps * 32
__device__ uint2 g_w6frag[8192];        // W6: 32 ntiles * 8 ksteps * 32
__device__ float g_part[2048 * 256];    // per-block partial AEV

__device__ __forceinline__ uint32_t cvta_sh(const void* p) {
    return (uint32_t)__cvta_generic_to_shared(p);
}
__device__ __forceinline__ void ldsm4(uint32_t* r, uint32_t addr) {
    asm volatile("ldmatrix.sync.aligned.m8n8.x4.shared.b16 {%0,%1,%2,%3}, [%4];"
        : "=r"(r[0]), "=r"(r[1]), "=r"(r[2]), "=r"(r[3]) : "r"(addr));
}
__device__ __forceinline__ void mma16816(float* d, const uint32_t* a, const uint32_t* b) {
    asm volatile("mma.sync.aligned.m16n8k16.row.col.f32.f16.f16.f32 "
        "{%0,%1,%2,%3}, {%4,%5,%6,%7}, {%8,%9}, {%0,%1,%2,%3};"
        : "+f"(d[0]), "+f"(d[1]), "+f"(d[2]), "+f"(d[3])
        : "r"(a[0]), "r"(a[1]), "r"(a[2]), "r"(a[3]), "r"(b[0]), "r"(b[1]));
}
// packed f16x2 tanh: 1 MUFU for 2 values (activations are stored f16 anyway)
__device__ __forceinline__ uint32_t tanh2(float a, float b) {
    __half2 h = __floats2half2_rn(a, b);
    uint32_t u = *reinterpret_cast<uint32_t*>(&h);
    uint32_t y;
    asm("tanh.approx.f16x2 %0, %1;" : "=r"(y) : "r"(u));
    return y;
}
__device__ __forceinline__ uint32_t hadd2u(uint32_t a, uint32_t b) {
    uint32_t y;
    asm("add.f16x2 %0, %1, %2;" : "=r"(y) : "r"(a), "r"(b));
    return y;
}
// f32 hardware tanh (1 MUFU, max rel err ~2^-11) — final layer
__device__ __forceinline__ float tanh_hw(float x) {
    float y;
    asm("tanh.approx.f32 %0, %1;" : "=f"(y) : "f"(x));
    return y;
}
__device__ __forceinline__ float fC_cut(float d) {
    return 0.5f * cosf(0.89759790102565521f * d) + 0.5f;
}

// pack W[K][N] fp32 -> B fragments. 14336 threads total.
__global__ void pack_weights(const float* __restrict__ W1, const float* __restrict__ W2,
                             const float* __restrict__ W3, const float* __restrict__ W4,
                             const float* __restrict__ W5, const float* __restrict__ W6) {
    int t = blockIdx.x * 256 + threadIdx.x;
    if (t >= 14336) return;
    int gi = t >> 5, l = t & 31;
    const float* W; uint2* dst; int rel, N, KS;
    if (gi < 128) {
        int L = gi >> 5; rel = gi & 31;
        W = (L == 0) ? W1 : (L == 1) ? W2 : (L == 2) ? W3 : W4;
        dst = g_w14frag + L * 1024; N = 64; KS = 4;
    } else if (gi < 192) {
        rel = gi - 128; W = W5; dst = g_w5frag; N = 128; KS = 4;
    } else {
        rel = gi - 192; W = W6; dst = g_w6frag; N = 256; KS = 8;
    }
    int nt = rel / KS, ks = rel % KS;
    int n = nt * 8 + (l >> 2);
    int k = ks * 16 + (l & 3) * 2;
    __half2 h0 = __floats2half2_rn(W[k * N + n], W[(k + 1) * N + n]);
    __half2 h1 = __floats2half2_rn(W[(k + 8) * N + n], W[(k + 9) * N + n]);
    uint2 u;
    u.x = *reinterpret_cast<uint32_t*>(&h0);
    u.y = *reinterpret_cast<uint32_t*>(&h1);
    dst[rel * 32 + l] = u;
}

__global__ void reduce_out(float* __restrict__ out) {
    int i = blockIdx.x * 512 + threadIdx.x;   // 262144 total
    int center = i >> 8, c = i & 255;
    out[i] = g_part[center * 512 + c] + g_part[center * 512 + 256 + c];
}

// 64->64 mma layer, warp owns 32 rows (2 m16 tiles).
// MODE 0: dst = tanh; MODE 1: dst = tanh + res; MODE 2: in-place (park chunk0)
template<int MODE>
__device__ __forceinline__ void layerG(char* sm8, int srcOff, int dstOff, int resOff,
                                       const uint2* __restrict__ frag,
                                       const float* bias, int lane, int R0)
{
    const int gid = lane >> 2, tig = lane & 3;
    uint32_t aBase = cvta_sh(sm8 + srcOff) + (R0 + (lane & 15)) * 144 + (lane >> 4) * 16;
    uint32_t parked[16];
    __syncwarp();
    #pragma unroll 1
    for (int nch = 0; nch < 2; nch++) {
        float acc[2][4][4];
        #pragma unroll
        for (int nt = 0; nt < 4; nt++) {
            float2 bc = *reinterpret_cast<const float2*>(bias + nch * 32 + nt * 8 + tig * 2);
            #pragma unroll
            for (int m = 0; m < 2; m++) {
                acc[m][nt][0] = bc.x; acc[m][nt][1] = bc.y;
                acc[m][nt][2] = bc.x; acc[m][nt][3] = bc.y;
            }
        }
        #pragma unroll
        for (int ks = 0; ks < 4; ks++) {
            uint32_t a[2][4];
            #pragma unroll
            for (int m = 0; m < 2; m++) ldsm4(a[m], aBase + m * 2304 + ks * 32);
            uint2 bw[4];
            #pragma unroll
            for (int nt = 0; nt < 4; nt++)
                bw[nt] = __ldg(frag + ((nch * 4 + nt) * 4 + ks) * 32 + lane);
            #pragma unroll
            for (int m = 0; m < 2; m++)
                #pragma unroll
                for (int nt = 0; nt < 4; nt++) {
                    uint32_t bb[2] = {bw[nt].x, bw[nt].y};
                    mma16816(acc[m][nt], a[m], bb);
                }
        }
        __syncwarp();
        #pragma unroll
        for (int m = 0; m < 2; m++) {
            #pragma unroll
            for (int nt = 0; nt < 4; nt++) {
                int col = nch * 32 + nt * 8 + tig * 2;
                int row = R0 + m * 16 + gid;
                uint32_t p01 = tanh2(acc[m][nt][0], acc[m][nt][1]);
                uint32_t p23 = tanh2(acc[m][nt][2], acc[m][nt][3]);
                if (MODE == 1) {
                    p01 = hadd2u(p01, *(uint32_t*)(sm8 + resOff + row * 144 + col * 2));
                    p23 = hadd2u(p23, *(uint32_t*)(sm8 + resOff + (row + 8) * 144 + col * 2));
                }
                if (MODE == 2 && nch == 0) {
                    parked[(m * 4 + nt) * 2]     = p01;
                    parked[(m * 4 + nt) * 2 + 1] = p23;
                } else {
                    *(uint32_t*)(sm8 + dstOff + row * 144 + col * 2) = p01;
                    *(uint32_t*)(sm8 + dstOff + (row + 8) * 144 + col * 2) = p23;
                }
            }
        }
    }
    if (MODE == 2) {
        __syncwarp();
        #pragma unroll
        for (int m = 0; m < 2; m++)
            #pragma unroll
            for (int nt = 0; nt < 4; nt++) {
                int col = nt * 8 + tig * 2;
                int row = R0 + m * 16 + gid;
                *(uint32_t*)(sm8 + dstOff + row * 144 + col * 2)       = parked[(m * 4 + nt) * 2];
                *(uint32_t*)(sm8 + dstOff + (row + 8) * 144 + col * 2) = parked[(m * 4 + nt) * 2 + 1];
            }
    }
}

// L5: 64 -> 128, src = P1 (blk2). cols 0-63 -> P0, 64-127 -> P1 (chunk2 parked).
__device__ __forceinline__ void layer5G(char* sm8, const float* bias, int lane, int R0)
{
    const int gid = lane >> 2, tig = lane & 3;
    uint32_t aBase = cvta_sh(sm8 + OFF_P1) + (R0 + (lane & 15)) * 144 + (lane >> 4) * 16;
    uint32_t parked[16];
    __syncwarp();
    #pragma unroll 1
    for (int nch = 0; nch < 4; nch++) {
        float acc[2][4][4];
        #pragma unroll
        for (int nt = 0; nt < 4; nt++) {
            float2 bc = *reinterpret_cast<const float2*>(bias + nch * 32 + nt * 8 + tig * 2);
            #pragma unroll
            for (int m = 0; m < 2; m++) {
                acc[m][nt][0] = bc.x; acc[m][nt][1] = bc.y;
                acc[m][nt][2] = bc.x; acc[m][nt][3] = bc.y;
            }
        }
        #pragma unroll
        for (int ks = 0; ks < 4; ks++) {
            uint32_t a[2][4];
            #pragma unroll
            for (int m = 0; m < 2; m++) ldsm4(a[m], aBase + m * 2304 + ks * 32);
            uint2 bw[4];
            #pragma unroll
            for (int nt = 0; nt < 4; nt++)
                bw[nt] = __ldg(g_w5frag + ((nch * 4 + nt) * 4 + ks) * 32 + lane);
            #pragma unroll
            for (int m = 0; m < 2; m++)
                #pragma unroll
                for (int nt = 0; nt < 4; nt++) {
                    uint32_t bb[2] = {bw[nt].x, bw[nt].y};
                    mma16816(acc[m][nt], a[m], bb);
                }
        }
        int dstOff = (nch < 2) ? OFF_P0 : OFF_P1;
        int dcol = (nch & 1) * 32;
        __syncwarp();
        #pragma unroll
        for (int m = 0; m < 2; m++) {
            #pragma unroll
            for (int nt = 0; nt < 4; nt++) {
                int col = dcol + nt * 8 + tig * 2;
                int row = R0 + m * 16 + gid;
                uint32_t p01 = tanh2(acc[m][nt][0], acc[m][nt][1]);
                uint32_t p23 = tanh2(acc[m][nt][2], acc[m][nt][3]);
                if (nch == 2) {
                    parked[(m * 4 + nt) * 2]     = p01;
                    parked[(m * 4 + nt) * 2 + 1] = p23;
                } else {
                    *(uint32_t*)(sm8 + dstOff + row * 144 + col * 2) = p01;
                    *(uint32_t*)(sm8 + dstOff + (row + 8) * 144 + col * 2) = p23;
                }
            }
        }
    }
    __syncwarp();
    #pragma unroll
    for (int m = 0; m < 2; m++)
        #pragma unroll
        for (int nt = 0; nt < 4; nt++) {
            int col = nt * 8 + tig * 2;
            int row = R0 + m * 16 + gid;
            *(uint32_t*)(sm8 + OFF_P1 + row * 144 + col * 2)       = parked[(m * 4 + nt) * 2];
            *(uint32_t*)(sm8 + OFF_P1 + (row + 8) * 144 + col * 2) = parked[(m * 4 + nt) * 2 + 1];
        }
}

// L6: 128 -> 256, epilogue f32 hw-tanh * smooth + reduce over warp rows -> AEV
__device__ __forceinline__ void layer6G(char* sm8, const float* bias, int lane, int R0, int wid)
{
    const int gid = lane >> 2, tig = lane & 3;
    uint32_t aBase0 = cvta_sh(sm8 + OFF_P0) + (R0 + (lane & 15)) * 144 + (lane >> 4) * 16;
    uint32_t aBase1 = cvta_sh(sm8 + OFF_P1) + (R0 + (lane & 15)) * 144 + (lane >> 4) * 16;
    const float* smoothF = (const float*)(sm8 + OFF_SMOOTH);
    float* aev = (float*)(sm8 + OFF_AEV) + wid * 256;
    float s[2][2];
    __syncwarp();
    #pragma unroll
    for (int m = 0; m < 2; m++) {
        s[m][0] = smoothF[R0 + m * 16 + gid];
        s[m][1] = smoothF[R0 + m * 16 + gid + 8];
    }
    #pragma unroll 1
    for (int nch = 0; nch < 8; nch++) {
        float acc[2][4][4];
        #pragma unroll
        for (int nt = 0; nt < 4; nt++) {
            float2 bc = *reinterpret_cast<const float2*>(bias + nch * 32 + nt * 8 + tig * 2);
            #pragma unroll
            for (int m = 0; m < 2; m++) {
                acc[m][nt][0] = bc.x; acc[m][nt][1] = bc.y;
                acc[m][nt][2] = bc.x; acc[m][nt][3] = bc.y;
            }
        }
        #pragma unroll
        for (int ks = 0; ks < 8; ks++) {
            uint32_t ab = (ks < 4) ? (aBase0 + ks * 32) : (aBase1 + (ks - 4) * 32);
            uint32_t a[2][4];
            #pragma unroll
            for (int m = 0; m < 2; m++) ldsm4(a[m], ab + m * 2304);
            uint2 bw[4];
            #pragma unroll
            for (int nt = 0; nt < 4; nt++)
                bw[nt] = __ldg(g_w6frag + ((nch * 4 + nt) * 8 + ks) * 32 + lane);
            #pragma unroll
            for (int m = 0; m < 2; m++)
                #pragma unroll
                for (int nt = 0; nt < 4; nt++) {
                    uint32_t bb[2] = {bw[nt].x, bw[nt].y};
                    mma16816(acc[m][nt], a[m], bb);
                }
        }
        float t0[4] = {0.f, 0.f, 0.f, 0.f}, t1[4] = {0.f, 0.f, 0.f, 0.f};
        #pragma unroll
        for (int m = 0; m < 2; m++)
            #pragma unroll
            for (int nt = 0; nt < 4; nt++) {
                t0[nt] += tanh_hw(acc[m][nt][0]) * s[m][0] + tanh_hw(acc[m][nt][2]) * s[m][1];
                t1[nt] += tanh_hw(acc[m][nt][1]) * s[m][0] + tanh_hw(acc[m][nt][3]) * s[m][1];
            }
        #pragma unroll
        for (int nt = 0; nt < 4; nt++) {
            #pragma unroll
            for (int sh = 4; sh < 32; sh <<= 1) {
                t0[nt] += __shfl_xor_sync(0xffffffffu, t0[nt], sh);
                t1[nt] += __shfl_xor_sync(0xffffffffu, t1[nt], sh);
            }
        }
        if (lane < 4) {
            #pragma unroll
            for (int nt = 0; nt < 4; nt++) {
                int col = nch * 32 + nt * 8 + lane * 2;
                aev[col] = t0[nt];
                aev[col + 1] = t1[nt];
            }
        }
    }
}

__global__ void __launch_bounds__(TPB, 2)
Obiwan_84335977825044_kernel(
    const float* __restrict__ gD, const float* __restrict__ gZ,
    const float* __restrict__ W0, const float* __restrict__ b0,
    const float* __restrict__ b1, const float* __restrict__ b2,
    const float* __restrict__ b3, const float* __restrict__ b4,
    const float* __restrict__ b5, const float* __restrict__ b6)
{
    extern __shared__ char sm8[];
    const int tid  = threadIdx.x;
    const int lane = tid & 31;
    const int wid  = tid >> 5;
    const int bidx = blockIdx.x;
    const int center = bidx >> 1;
    const int half = bidx & 1;
    const int b    = center >> 5;
    const int ictr = center & 31;

    float* W0F   = (float*)(sm8 + OFF_W0);
    float* biasF = (float*)(sm8 + OFF_BIAS);
    float* smF   = (float*)(sm8 + OFF_SMOOTH);
    float* sDF   = (float*)(sm8 + OFF_D);
    float* sZF   = (float*)(sm8 + OFF_Z);

    // ---- staging (small) ----
    for (int i = tid; i < 1024; i += TPB) sDF[i] = gD[b * 1024 + i];
    if (tid < 32) sZF[tid] = gZ[b * 32 + tid];
    for (int i = tid; i < 576; i += TPB) W0F[i] = W0[i];
    if (tid < 64) {
        biasF[tid] = b0[tid]; biasF[64 + tid] = b1[tid]; biasF[128 + tid] = b2[tid];
        biasF[192 + tid] = b3[tid]; biasF[256 + tid] = b4[tid];
    }
    if (tid < 128) biasF[320 + tid] = b5[tid];
    for (int i = tid; i < 256; i += TPB) biasF[448 + i] = b6[i];
    __syncthreads();

    // ---- L0 (scalar fp32): one row per thread ----
    {
        int r = half * 256 + tid;
        bool valid = (r < 465);
        int rem = valid ? r : 0;
        int a = 0;
        while (rem >= 30 - a) { rem -= 30 - a; a++; }
        int bb2 = a + 1 + rem;
        int j = a + (a >= ictr);
        int k = bb2 + (bb2 >= ictr);

        float Rij = sDF[ictr * 32 + j];
        float Rik = sDF[ictr * 32 + k];
        float Rjk = sDF[j * 32 + k];
        float zi = sZF[ictr], zj = sZF[j], zk = sZF[k];

        float rij2 = Rij * Rij, rik2 = Rik * Rik, rjk2 = Rjk * Rjk;
        float ci = (rij2 + rik2 - rjk2) / fmaxf(2.f * Rij * Rik, 1e-10f);
        float cj = (rij2 + rjk2 - rik2) / fmaxf(2.f * Rij * Rjk, 1e-10f);
        float ck = (rik2 + rjk2 - rij2) / fmaxf(2.f * Rik * Rjk, 1e-10f);

        float g0 = Rij + Rik + Rjk;
        float g1 = Rij * Rik + Rij * Rjk + Rik * Rjk;
        float g2 = Rij * Rik * Rjk;

        float h0 = zi + zj + zk;
        float h1 = ci + cj + ck;
        float h2 = zi * (zj + zk) + zj * zk - ci * (cj + ck) - cj * ck;
        float h3 = zi * (cj + ck) + ci * (zj + zk) + zj * ck + cj * zk;
        float h4 = zi * (zj * zk - cj * ck) - ci * (zj * ck + cj * zk);
        float h5 = zi * (zj * ck + cj * zk) + ci * (zj * zk - cj * ck);

        float ign = 1.f / (sqrtf(g0 * g0 + g1 * g1 + g2 * g2) + 1e-7f);
        float icn = 1.f / (sqrtf(h0 * h0 + h1 * h1 + h2 * h2 + h3 * h3 + h4 * h4 + h5 * h5) + 1e-7f);

        float smooth = 0.f;
        if (valid && Rij < 3.5f && Rik < 3.5f) smooth = fC_cut(Rij) * fC_cut(Rik);
        smF[tid] = smooth;

        float in9[9];
        in9[0] = g0 * ign; in9[1] = g1 * ign; in9[2] = g2 * ign;
        in9[3] = h0 * icn; in9[4] = h1 * icn; in9[5] = h2 * icn;
        in9[6] = h3 * icn; in9[7] = h4 * icn; in9[8] = h5 * icn;
        if (!valid) {
            #pragma unroll
            for (int q = 0; q < 9; q++) in9[q] = 0.f;
        }

        float acc[64];
        #pragma unroll
        for (int o = 0; o < 64; o += 4) {
            float4 bbv = *reinterpret_cast<const float4*>(biasF + o);
            acc[o] = bbv.x; acc[o + 1] = bbv.y; acc[o + 2] = bbv.z; acc[o + 3] = bbv.w;
        }
        #pragma unroll 1
        for (int kk = 0; kk < 9; kk++) {
            float xk = in9[kk];
            const float4* w4 = reinterpret_cast<const float4*>(W0F + kk * 64);
            #pragma unroll
            for (int o = 0; o < 64; o += 4) {
                float4 w = w4[o >> 2];
                acc[o]     = fmaf(xk, w.x, acc[o]);
                acc[o + 1] = fmaf(xk, w.y, acc[o + 1]);
                acc[o + 2] = fmaf(xk, w.z, acc[o + 2]);
                acc[o + 3] = fmaf(xk, w.w, acc[o + 3]);
            }
        }
        #pragma unroll
        for (int o = 0; o < 64; o += 2) {
            *(uint32_t*)(sm8 + OFF_P0 + tid * 144 + o * 2) = tanh2(acc[o], acc[o + 1]);
        }
    }
    __syncthreads();

    // ---- warp-tiled MLP: each warp owns rows [32*wid, 32*wid+32) ----
    const int R0 = wid * 32;
    layerG<1>(sm8, OFF_P0, OFF_P1, OFF_P0, g_w14frag,        biasF + 64,  lane, R0); // blk1
    layerG<0>(sm8, OFF_P1, OFF_P0, 0,      g_w14frag + 1024, biasF + 128, lane, R0);
    layerG<2>(sm8, OFF_P0, OFF_P0, 0,      g_w14frag + 2048, biasF + 192, lane, R0);
    layerG<1>(sm8, OFF_P0, OFF_P1, OFF_P1, g_w14frag + 3072, biasF + 256, lane, R0); // blk2
    layer5G(sm8, biasF + 320, lane, R0);                                             // blk3
    layer6G(sm8, biasF + 448, lane, R0, wid);

    // ---- block reduce, write partial ----
    __syncthreads();
    float* aevF = (float*)(sm8 + OFF_AEV);
    float sum = 0.f;
    #pragma unroll
    for (int w = 0; w < 8; ++w) sum += aevF[w * 256 + tid];
    g_part[bidx * 256 + tid] = sum;
}

extern "C" void kernel_launch(void* const* d_in, const int* in_sizes, int n_in,
                              void* d_out, int out_size) {
    const float* D  = (const float*)d_in[0];
    const float* Z  = (const float*)d_in[1];
    const float* W0 = (const float*)d_in[2];  const float* b0 = (const float*)d_in[3];
    const float* W1 = (const float*)d_in[4];  const float* b1 = (const float*)d_in[5];
    const float* W2 = (const float*)d_in[6];  const float* b2 = (const float*)d_in[7];
    const float* W3 = (const float*)d_in[8];  const float* b3 = (const float*)d_in[9];
    const float* W4 = (const float*)d_in[10]; const float* b4 = (const float*)d_in[11];
    const float* W5 = (const float*)d_in[12]; const float* b5 = (const float*)d_in[13];
    const float* W6 = (const float*)d_in[14]; const float* b6 = (const float*)d_in[15];

    pack_weights<<<56, 256>>>(W1, W2, W3, W4, W5, W6);

    cudaFuncSetAttribute(Obiwan_84335977825044_kernel,
                         cudaFuncAttributeMaxDynamicSharedMemorySize, SMEM_BYTES);
    Obiwan_84335977825044_kernel<<<2048, TPB, SMEM_BYTES>>>(
        D, Z, W0, b0, b1, b2, b3, b4, b5, b6);

    reduce_out<<<512, 512>>>((float*)d_out);
}

// round 8
// speedup vs baseline: 18.6983x; 1.0305x over previous
#include <cuda_runtime.h>
#include <cuda_fp16.h>
#include <stdint.h>

#define TPB 256

// ---- dynamic smem layout (byte offsets) ----
#define OFF_P0     0         // plane0 fp16 [256][72]
#define OFF_P1     36864     // plane1 fp16 [256][72]
#define OFF_D      73728     // 1024 fp32
#define OFF_Z      77824     // 32 fp32
#define OFF_SMOOTH 77952     // 256 fp32
#define OFF_BIAS   78976     // 704 fp32: b0|b1|b2|b3|b4|b5|b6
#define OFF_AEV    81792     // 8 warps * 256 fp32
#define OFF_W0     89984     // 576 fp32
#define SMEM_BYTES 92288

// weight fragments packed as PAIRS of adjacent n-tiles -> one uint4 (LDG.128)
// layout: ((nch*2 + p)*KS + ks)*32 + lane
__device__ uint4 g_w14frag[2048];   // W1..W4: 512 uint4 per layer
__device__ uint4 g_w5frag[1024];    // W5
__device__ uint4 g_w6frag[4096];    // W6
__device__ float g_part[2048 * 256];

__device__ __forceinline__ uint32_t cvta_sh(const void* p) {
    return (uint32_t)__cvta_generic_to_shared(p);
}
__device__ __forceinline__ void ldsm4(uint32_t* r, uint32_t addr) {
    asm volatile("ldmatrix.sync.aligned.m8n8.x4.shared.b16 {%0,%1,%2,%3}, [%4];"
        : "=r"(r[0]), "=r"(r[1]), "=r"(r[2]), "=r"(r[3]) : "r"(addr));
}
__device__ __forceinline__ void mma16816(float* d, const uint32_t* a, uint32_t b0, uint32_t b1) {
    asm volatile("mma.sync.aligned.m16n8k16.row.col.f32.f16.f16.f32 "
        "{%0,%1,%2,%3}, {%4,%5,%6,%7}, {%8,%9}, {%0,%1,%2,%3};"
        : "+f"(d[0]), "+f"(d[1]), "+f"(d[2]), "+f"(d[3])
        : "r"(a[0]), "r"(a[1]), "r"(a[2]), "r"(a[3]), "r"(b0), "r"(b1));
}
__device__ __forceinline__ uint32_t tanh2(float a, float b) {
    __half2 h = __floats2half2_rn(a, b);
    uint32_t u = *reinterpret_cast<uint32_t*>(&h);
    uint32_t y;
    asm("tanh.approx.f16x2 %0, %1;" : "=r"(y) : "r"(u));
    return y;
}
__device__ __forceinline__ uint32_t hadd2u(uint32_t a, uint32_t b) {
    uint32_t y;
    asm("add.f16x2 %0, %1, %2;" : "=r"(y) : "r"(a), "r"(b));
    return y;
}
__device__ __forceinline__ float tanh_hw(float x) {
    float y;
    asm("tanh.approx.f32 %0, %1;" : "=f"(y) : "f"(x));
    return y;
}
__device__ __forceinline__ float fC_cut(float d) {
    return 0.5f * cosf(0.89759790102565521f * d) + 0.5f;
}

// pack weights into PAIRED B fragments. 7168 threads.
__global__ void pack_weights(const float* __restrict__ W1, const float* __restrict__ W2,
                             const float* __restrict__ W3, const float* __restrict__ W4,
                             const float* __restrict__ W5, const float* __restrict__ W6) {
    int t = blockIdx.x * 256 + threadIdx.x;
    if (t >= 7168) return;
    int gi = t >> 5, l = t & 31;
    const float* W; uint4* dst; int nch, p, ks, N, idx;
    if (gi < 64) {               // W1..W4: 16 gi per layer
        int L = gi >> 4, rel = gi & 15;
        W = (L == 0) ? W1 : (L == 1) ? W2 : (L == 2) ? W3 : W4;
        nch = rel >> 3; p = (rel >> 2) & 1; ks = rel & 3;
        dst = g_w14frag + L * 512; N = 64;
        idx = ((nch * 2 + p) * 4 + ks) * 32 + l;
    } else if (gi < 96) {        // W5
        int rel = gi - 64;
        W = W5; nch = rel >> 3; p = (rel >> 2) & 1; ks = rel & 3;
        dst = g_w5frag; N = 128;
        idx = ((nch * 2 + p) * 4 + ks) * 32 + l;
    } else {                     // W6
        int rel = gi - 96;
        W = W6; nch = rel >> 4; p = (rel >> 3) & 1; ks = rel & 7;
        dst = g_w6frag; N = 256;
        idx = ((nch * 2 + p) * 8 + ks) * 32 + l;
    }
    int k = ks * 16 + (l & 3) * 2;
    int r = l >> 2;
    uint4 u;
    {
        int n = (nch * 4 + 2 * p) * 8 + r;
        __half2 h0 = __floats2half2_rn(W[k * N + n], W[(k + 1) * N + n]);
        __half2 h1 = __floats2half2_rn(W[(k + 8) * N + n], W[(k + 9) * N + n]);
        u.x = *reinterpret_cast<uint32_t*>(&h0);
        u.y = *reinterpret_cast<uint32_t*>(&h1);
    }
    {
        int n = (nch * 4 + 2 * p + 1) * 8 + r;
        __half2 h0 = __floats2half2_rn(W[k * N + n], W[(k + 1) * N + n]);
        __half2 h1 = __floats2half2_rn(W[(k + 8) * N + n], W[(k + 9) * N + n]);
        u.z = *reinterpret_cast<uint32_t*>(&h0);
        u.w = *reinterpret_cast<uint32_t*>(&h1);
    }
    dst[idx] = u;
}

__global__ void reduce_out(float* __restrict__ out) {
    int i = blockIdx.x * 512 + threadIdx.x;
    int center = i >> 8, c = i & 255;
    out[i] = g_part[center * 512 + c] + g_part[center * 512 + 256 + c];
}

// 64->64 mma layer, warp owns 32 rows. A fragments hoisted across n-chunks.
// MODE 0: dst = tanh; MODE 1: dst = tanh + res; MODE 2: in-place (park chunk0)
template<int MODE>
__device__ __forceinline__ void layerG(char* sm8, int srcOff, int dstOff, int resOff,
                                       const uint4* __restrict__ frag,
                                       const float* bias, int lane, int R0)
{
    const int gid = lane >> 2, tig = lane & 3;
    uint32_t aBase = cvta_sh(sm8 + srcOff) + (R0 + (lane & 15)) * 144 + (lane >> 4) * 16;
    uint32_t parked[16];
    __syncwarp();
    uint32_t a[4][2][4];                       // [ks][m][4] — loaded once
    #pragma unroll
    for (int ks = 0; ks < 4; ks++)
        #pragma unroll
        for (int m = 0; m < 2; m++) ldsm4(a[ks][m], aBase + m * 2304 + ks * 32);
    #pragma unroll 1
    for (int nch = 0; nch < 2; nch++) {
        float acc[2][4][4];
        #pragma unroll
        for (int nt = 0; nt < 4; nt++) {
            float2 bc = *reinterpret_cast<const float2*>(bias + nch * 32 + nt * 8 + tig * 2);
            #pragma unroll
            for (int m = 0; m < 2; m++) {
                acc[m][nt][0] = bc.x; acc[m][nt][1] = bc.y;
                acc[m][nt][2] = bc.x; acc[m][nt][3] = bc.y;
            }
        }
        #pragma unroll
        for (int ks = 0; ks < 4; ks++) {
            uint4 bw0 = __ldg(frag + ((nch * 2 + 0) * 4 + ks) * 32 + lane);
            uint4 bw1 = __ldg(frag + ((nch * 2 + 1) * 4 + ks) * 32 + lane);
            #pragma unroll
            for (int m = 0; m < 2; m++) {
                mma16816(acc[m][0], a[ks][m], bw0.x, bw0.y);
                mma16816(acc[m][1], a[ks][m], bw0.z, bw0.w);
                mma16816(acc[m][2], a[ks][m], bw1.x, bw1.y);
                mma16816(acc[m][3], a[ks][m], bw1.z, bw1.w);
            }
        }
        __syncwarp();
        #pragma unroll
        for (int m = 0; m < 2; m++) {
            #pragma unroll
            for (int nt = 0; nt < 4; nt++) {
                int col = nch * 32 + nt * 8 + tig * 2;
                int row = R0 + m * 16 + gid;
                uint32_t p01 = tanh2(acc[m][nt][0], acc[m][nt][1]);
                uint32_t p23 = tanh2(acc[m][nt][2], acc[m][nt][3]);
                if (MODE == 1) {
                    p01 = hadd2u(p01, *(uint32_t*)(sm8 + resOff + row * 144 + col * 2));
                    p23 = hadd2u(p23, *(uint32_t*)(sm8 + resOff + (row + 8) * 144 + col * 2));
                }
                if (MODE == 2 && nch == 0) {
                    parked[(m * 4 + nt) * 2]     = p01;
                    parked[(m * 4 + nt) * 2 + 1] = p23;
                } else {
                    *(uint32_t*)(sm8 + dstOff + row * 144 + col * 2) = p01;
                    *(uint32_t*)(sm8 + dstOff + (row + 8) * 144 + col * 2) = p23;
                }
            }
        }
    }
    if (MODE == 2) {
        __syncwarp();
        #pragma unroll
        for (int m = 0; m < 2; m++)
            #pragma unroll
            for (int nt = 0; nt < 4; nt++) {
                int col = nt * 8 + tig * 2;
                int row = R0 + m * 16 + gid;
                *(uint32_t*)(sm8 + dstOff + row * 144 + col * 2)       = parked[(m * 4 + nt) * 2];
                *(uint32_t*)(sm8 + dstOff + (row + 8) * 144 + col * 2) = parked[(m * 4 + nt) * 2 + 1];
            }
    }
}

// L5: 64 -> 128. A hoisted; cols 0-63 -> P0, 64-127 -> P1 (chunk2 parked).
__device__ __forceinline__ void layer5G(char* sm8, const float* bias, int lane, int R0)
{
    const int gid = lane >> 2, tig = lane & 3;
    uint32_t aBase = cvta_sh(sm8 + OFF_P1) + (R0 + (lane & 15)) * 144 + (lane >> 4) * 16;
    uint32_t parked[16];
    __syncwarp();
    uint32_t a[4][2][4];
    #pragma unroll
    for (int ks = 0; ks < 4; ks++)
        #pragma unroll
        for (int m = 0; m < 2; m++) ldsm4(a[ks][m], aBase + m * 2304 + ks * 32);
    #pragma unroll 1
    for (int nch = 0; nch < 4; nch++) {
        float acc[2][4][4];
        #pragma unroll
        for (int nt = 0; nt < 4; nt++) {
            float2 bc = *reinterpret_cast<const float2*>(bias + nch * 32 + nt * 8 + tig * 2);
            #pragma unroll
            for (int m = 0; m < 2; m++) {
                acc[m][nt][0] = bc.x; acc[m][nt][1] = bc.y;
                acc[m][nt][2] = bc.x; acc[m][nt][3] = bc.y;
            }
        }
        #pragma unroll
        for (int ks = 0; ks < 4; ks++) {
            uint4 bw0 = __ldg(g_w5frag + ((nch * 2 + 0) * 4 + ks) * 32 + lane);
            uint4 bw1 = __ldg(g_w5frag + ((nch * 2 + 1) * 4 + ks) * 32 + lane);
            #pragma unroll
            for (int m = 0; m < 2; m++) {
                mma16816(acc[m][0], a[ks][m], bw0.x, bw0.y);
                mma16816(acc[m][1], a[ks][m], bw0.z, bw0.w);
                mma16816(acc[m][2], a[ks][m], bw1.x, bw1.y);
                mma16816(acc[m][3], a[ks][m], bw1.z, bw1.w);
            }
        }
        int dstOff = (nch < 2) ? OFF_P0 : OFF_P1;
        int dcol = (nch & 1) * 32;
        __syncwarp();
        #pragma unroll
        for (int m = 0; m < 2; m++) {
            #pragma unroll
            for (int nt = 0; nt < 4; nt++) {
                int col = dcol + nt * 8 + tig * 2;
                int row = R0 + m * 16 + gid;
                uint32_t p01 = tanh2(acc[m][nt][0], acc[m][nt][1]);
                uint32_t p23 = tanh2(acc[m][nt][2], acc[m][nt][3]);
                if (nch == 2) {
                    parked[(m * 4 + nt) * 2]     = p01;
                    parked[(m * 4 + nt) * 2 + 1] = p23;
                } else {
                    *(uint32_t*)(sm8 + dstOff + row * 144 + col * 2) = p01;
                    *(uint32_t*)(sm8 + dstOff + (row + 8) * 144 + col * 2) = p23;
                }
            }
        }
    }
    __syncwarp();
    #pragma unroll
    for (int m = 0; m < 2; m++)
        #pragma unroll
        for (int nt = 0; nt < 4; nt++) {
            int col = nt * 8 + tig * 2;
            int row = R0 + m * 16 + gid;
            *(uint32_t*)(sm8 + OFF_P1 + row * 144 + col * 2)       = parked[(m * 4 + nt) * 2];
            *(uint32_t*)(sm8 + OFF_P1 + (row + 8) * 144 + col * 2) = parked[(m * 4 + nt) * 2 + 1];
        }
}

// L6: 128 -> 256, epilogue f32 hw-tanh * smooth + reduce -> AEV
__device__ __forceinline__ void layer6G(char* sm8, const float* bias, int lane, int R0, int wid)
{
    const int gid = lane >> 2, tig = lane & 3;
    uint32_t aBase0 = cvta_sh(sm8 + OFF_P0) + (R0 + (lane & 15)) * 144 + (lane >> 4) * 16;
    uint32_t aBase1 = cvta_sh(sm8 + OFF_P1) + (R0 + (lane & 15)) * 144 + (lane >> 4) * 16;
    const float* smoothF = (const float*)(sm8 + OFF_SMOOTH);
    float* aev = (float*)(sm8 + OFF_AEV) + wid * 256;
    float s[2][2];
    __syncwarp();
    #pragma unroll
    for (int m = 0; m < 2; m++) {
        s[m][0] = smoothF[R0 + m * 16 + gid];
        s[m][1] = smoothF[R0 + m * 16 + gid + 8];
    }
    #pragma unroll 1
    for (int nch = 0; nch < 8; nch++) {
        float acc[2][4][4];
        #pragma unroll
        for (int nt = 0; nt < 4; nt++) {
            float2 bc = *reinterpret_cast<const float2*>(bias + nch * 32 + nt * 8 + tig * 2);
            #pragma unroll
            for (int m = 0; m < 2; m++) {
                acc[m][nt][0] = bc.x; acc[m][nt][1] = bc.y;
                acc[m][nt][2] = bc.x; acc[m][nt][3] = bc.y;
            }
        }
        #pragma unroll
        for (int ks = 0; ks < 8; ks++) {
            uint32_t ab = (ks < 4) ? (aBase0 + ks * 32) : (aBase1 + (ks - 4) * 32);
            uint32_t a[2][4];
            #pragma unroll
            for (int m = 0; m < 2; m++) ldsm4(a[m], ab + m * 2304);
            uint4 bw0 = __ldg(g_w6frag + ((nch * 2 + 0) * 8 + ks) * 32 + lane);
            uint4 bw1 = __ldg(g_w6frag + ((nch * 2 + 1) * 8 + ks) * 32 + lane);
            #pragma unroll
            for (int m = 0; m < 2; m++) {
                mma16816(acc[m][0], a[m], bw0.x, bw0.y);
                mma16816(acc[m][1], a[m], bw0.z, bw0.w);
                mma16816(acc[m][2], a[m], bw1.x, bw1.y);
                mma16816(acc[m][3], a[m], bw1.z, bw1.w);
            }
        }
        float t0[4] = {0.f, 0.f, 0.f, 0.f}, t1[4] = {0.f, 0.f, 0.f, 0.f};
        #pragma unroll
        for (int m = 0; m < 2; m++)
            #pragma unroll
            for (int nt = 0; nt < 4; nt++) {
                t0[nt] += tanh_hw(acc[m][nt][0]) * s[m][0] + tanh_hw(acc[m][nt][2]) * s[m][1];
                t1[nt] += tanh_hw(acc[m][nt][1]) * s[m][0] + tanh_hw(acc[m][nt][3]) * s[m][1];
            }
        #pragma unroll
        for (int nt = 0; nt < 4; nt++) {
            #pragma unroll
            for (int sh = 4; sh < 32; sh <<= 1) {
                t0[nt] += __shfl_xor_sync(0xffffffffu, t0[nt], sh);
                t1[nt] += __shfl_xor_sync(0xffffffffu, t1[nt], sh);
            }
        }
        if (lane < 4) {
            #pragma unroll
            for (int nt = 0; nt < 4; nt++) {
                int col = nch * 32 + nt * 8 + lane * 2;
                aev[col] = t0[nt];
                aev[col + 1] = t1[nt];
            }
        }
    }
}

__global__ void __launch_bounds__(TPB, 2)
Obiwan_84335977825044_kernel(
    const float* __restrict__ gD, const float* __restrict__ gZ,
    const float* __restrict__ W0, const float* __restrict__ b0,
    const float* __restrict__ b1, const float* __restrict__ b2,
    const float* __restrict__ b3, const float* __restrict__ b4,
    const float* __restrict__ b5, const float* __restrict__ b6)
{
    extern __shared__ char sm8[];
    const int tid  = threadIdx.x;
    const int lane = tid & 31;
    const int wid  = tid >> 5;
    const int bidx = blockIdx.x;
    const int center = bidx >> 1;
    const int half = bidx & 1;
    const int b    = center >> 5;
    const int ictr = center & 31;

    float* W0F   = (float*)(sm8 + OFF_W0);
    float* biasF = (float*)(sm8 + OFF_BIAS);
    float* smF   = (float*)(sm8 + OFF_SMOOTH);
    float* sDF   = (float*)(sm8 + OFF_D);
    float* sZF   = (float*)(sm8 + OFF_Z);

    // ---- staging (small) ----
    for (int i = tid; i < 1024; i += TPB) sDF[i] = gD[b * 1024 + i];
    if (tid < 32) sZF[tid] = gZ[b * 32 + tid];
    for (int i = tid; i < 576; i += TPB) W0F[i] = W0[i];
    if (tid < 64) {
        biasF[tid] = b0[tid]; biasF[64 + tid] = b1[tid]; biasF[128 + tid] = b2[tid];
        biasF[192 + tid] = b3[tid]; biasF[256 + tid] = b4[tid];
    }
    if (tid < 128) biasF[320 + tid] = b5[tid];
    for (int i = tid; i < 256; i += TPB) biasF[448 + i] = b6[i];
    __syncthreads();

    // ---- L0 (scalar fp32): one row per thread ----
    {
        int r = half * 256 + tid;
        bool valid = (r < 465);
        int rem = valid ? r : 0;
        int a = 0;
        while (rem >= 30 - a) { rem -= 30 - a; a++; }
        int bb2 = a + 1 + rem;
        int j = a + (a >= ictr);
        int k = bb2 + (bb2 >= ictr);

        float Rij = sDF[ictr * 32 + j];
        float Rik = sDF[ictr * 32 + k];
        float Rjk = sDF[j * 32 + k];
        float zi = sZF[ictr], zj = sZF[j], zk = sZF[k];

        float rij2 = Rij * Rij, rik2 = Rik * Rik, rjk2 = Rjk * Rjk;
        float ci = (rij2 + rik2 - rjk2) / fmaxf(2.f * Rij * Rik, 1e-10f);
        float cj = (rij2 + rjk2 - rik2) / fmaxf(2.f * Rij * Rjk, 1e-10f);
        float ck = (rik2 + rjk2 - rij2) / fmaxf(2.f * Rik * Rjk, 1e-10f);

        float g0 = Rij + Rik + Rjk;
        float g1 = Rij * Rik + Rij * Rjk + Rik * Rjk;
        float g2 = Rij * Rik * Rjk;

        float h0 = zi + zj + zk;
        float h1 = ci + cj + ck;
        float h2 = zi * (zj + zk) + zj * zk - ci * (cj + ck) - cj * ck;
        float h3 = zi * (cj + ck) + ci * (zj + zk) + zj * ck + cj * zk;
        float h4 = zi * (zj * zk - cj * ck) - ci * (zj * ck + cj * zk);
        float h5 = zi * (zj * ck + cj * zk) + ci * (zj * zk - cj * ck);

        float ign = 1.f / (sqrtf(g0 * g0 + g1 * g1 + g2 * g2) + 1e-7f);
        float icn = 1.f / (sqrtf(h0 * h0 + h1 * h1 + h2 * h2 + h3 * h3 + h4 * h4 + h5 * h5) + 1e-7f);

        float smooth = 0.f;
        if (valid && Rij < 3.5f && Rik < 3.5f) smooth = fC_cut(Rij) * fC_cut(Rik);
        smF[tid] = smooth;

        float in9[9];
        in9[0] = g0 * ign; in9[1] = g1 * ign; in9[2] = g2 * ign;
        in9[3] = h0 * icn; in9[4] = h1 * icn; in9[5] = h2 * icn;
        in9[6] = h3 * icn; in9[7] = h4 * icn; in9[8] = h5 * icn;
        if (!valid) {
            #pragma unroll
            for (int q = 0; q < 9; q++) in9[q] = 0.f;
        }

        float acc[64];
        #pragma unroll
        for (int o = 0; o < 64; o += 4) {
            float4 bbv = *reinterpret_cast<const float4*>(biasF + o);
            acc[o] = bbv.x; acc[o + 1] = bbv.y; acc[o + 2] = bbv.z; acc[o + 3] = bbv.w;
        }
        #pragma unroll 1
        for (int kk = 0; kk < 9; kk++) {
            float xk = in9[kk];
            const float4* w4 = reinterpret_cast<const float4*>(W0F + kk * 64);
            #pragma unroll
            for (int o = 0; o < 64; o += 4) {
                float4 w = w4[o >> 2];
                acc[o]     = fmaf(xk, w.x, acc[o]);
                acc[o + 1] = fmaf(xk, w.y, acc[o + 1]);
                acc[o + 2] = fmaf(xk, w.z, acc[o + 2]);
                acc[o + 3] = fmaf(xk, w.w, acc[o + 3]);
            }
        }
        #pragma unroll
        for (int o = 0; o < 64; o += 2) {
            *(uint32_t*)(sm8 + OFF_P0 + tid * 144 + o * 2) = tanh2(acc[o], acc[o + 1]);
        }
    }
    __syncthreads();

    // ---- warp-tiled MLP: each warp owns rows [32*wid, 32*wid+32) ----
    const int R0 = wid * 32;
    layerG<1>(sm8, OFF_P0, OFF_P1, OFF_P0, g_w14frag,        biasF + 64,  lane, R0); // blk1
    layerG<0>(sm8, OFF_P1, OFF_P0, 0,      g_w14frag + 512,  biasF + 128, lane, R0);
    layerG<2>(sm8, OFF_P0, OFF_P0, 0,      g_w14frag + 1024, biasF + 192, lane, R0);
    layerG<1>(sm8, OFF_P0, OFF_P1, OFF_P1, g_w14frag + 1536, biasF + 256, lane, R0); // blk2
    layer5G(sm8, biasF + 320, lane, R0);                                             // blk3
    layer6G(sm8, biasF + 448, lane, R0, wid);

    // ---- block reduce, write partial ----
    __syncthreads();
    float* aevF = (float*)(sm8 + OFF_AEV);
    float sum = 0.f;
    #pragma unroll
    for (int w = 0; w < 8; ++w) sum += aevF[w * 256 + tid];
    g_part[bidx * 256 + tid] = sum;
}

extern "C" void kernel_launch(void* const* d_in, const int* in_sizes, int n_in,
                              void* d_out, int out_size) {
    const float* D  = (const float*)d_in[0];
    const float* Z  = (const float*)d_in[1];
    const float* W0 = (const float*)d_in[2];  const float* b0 = (const float*)d_in[3];
    const float* W1 = (const float*)d_in[4];  const float* b1 = (const float*)d_in[5];
    const float* W2 = (const float*)d_in[6];  const float* b2 = (const float*)d_in[7];
    const float* W3 = (const float*)d_in[8];  const float* b3 = (const float*)d_in[9];
    const float* W4 = (const float*)d_in[10]; const float* b4 = (const float*)d_in[11];
    const float* W5 = (const float*)d_in[12]; const float* b5 = (const float*)d_in[13];
    const float* W6 = (const float*)d_in[14]; const float* b6 = (const float*)d_in[15];

    pack_weights<<<28, 256>>>(W1, W2, W3, W4, W5, W6);

    cudaFuncSetAttribute(Obiwan_84335977825044_kernel,
                         cudaFuncAttributeMaxDynamicSharedMemorySize, SMEM_BYTES);
    Obiwan_84335977825044_kernel<<<2048, TPB, SMEM_BYTES>>>(
        D, Z, W0, b0, b1, b2, b3, b4, b5, b6);

    reduce_out<<<512, 512>>>((float*)d_out);
}